// round 2
// baseline (speedup 1.0000x reference)
#include <cuda_runtime.h>
#include <math.h>

#define SEQ 4096
#define EMB 768
#define NH  12
#define HD  64

// Scratch (allocation-free rule: __device__ globals).
// g_qkv: [which(q,k,v)][head][seq][hd]
__device__ float g_qkv[3 * NH * SEQ * HD];
// g_attn: [head][seq][hd]
__device__ float g_attn[NH * SEQ * HD];

__device__ __forceinline__ void fma16(float (&acc)[4][4],
                                      float a0, float a1, float a2, float a3,
                                      float4 b) {
    acc[0][0] += a0 * b.x; acc[0][1] += a0 * b.y; acc[0][2] += a0 * b.z; acc[0][3] += a0 * b.w;
    acc[1][0] += a1 * b.x; acc[1][1] += a1 * b.y; acc[1][2] += a1 * b.z; acc[1][3] += a1 * b.w;
    acc[2][0] += a2 * b.x; acc[2][1] += a2 * b.y; acc[2][2] += a2 * b.z; acc[2][3] += a2 * b.w;
    acc[3][0] += a3 * b.x; acc[3][1] += a3 * b.y; acc[3][2] += a3 * b.z; acc[3][3] += a3 * b.w;
}

// ---------------------------------------------------------------------------
// Kernel 1: QKV projections.  y = x @ W + b, written head-major into g_qkv.
// Grid: (head=12, mtile=64, which=3). Block 256 = 16x16, 4x4 micro-tile.
// BM=BN=64, BK=16. One head == one 64-wide N tile, so the epilogue is trivial.
// ---------------------------------------------------------------------------
__global__ __launch_bounds__(256) void proj_qkv(
    const float* __restrict__ x,
    const float* __restrict__ Wq, const float* __restrict__ bq,
    const float* __restrict__ Wk, const float* __restrict__ bk,
    const float* __restrict__ Wv, const float* __restrict__ bv)
{
    __shared__ float As[16][65];   // A^T tile (pad 65: avoid transpose-store conflicts)
    __shared__ float Bs[16][64];

    const int which = blockIdx.z;
    const float* W    = (which == 0) ? Wq : (which == 1) ? Wk : Wv;
    const float* bias = (which == 0) ? bq : (which == 1) ? bk : bv;
    const int head = blockIdx.x;
    const int n0 = head * 64;
    const int m0 = blockIdx.y * 64;
    const int tid = threadIdx.x;
    const int tx = tid & 15, ty = tid >> 4;
    const int arow = tid >> 2, acg = tid & 3;     // A loader: 64 rows x 4 float4
    const int brow = tid >> 4, bcg = tid & 15;    // B loader: 16 rows x 16 float4

    float acc[4][4] = {};

    for (int k0 = 0; k0 < EMB; k0 += 16) {
        float4 av = *(const float4*)&x[(size_t)(m0 + arow) * EMB + k0 + acg * 4];
        float4 bw = *(const float4*)&W[(size_t)(k0 + brow) * EMB + n0 + bcg * 4];
        As[acg * 4 + 0][arow] = av.x;
        As[acg * 4 + 1][arow] = av.y;
        As[acg * 4 + 2][arow] = av.z;
        As[acg * 4 + 3][arow] = av.w;
        *(float4*)&Bs[brow][bcg * 4] = bw;
        __syncthreads();
        #pragma unroll
        for (int kk = 0; kk < 16; kk++) {
            float4 b4 = *(const float4*)&Bs[kk][tx * 4];
            float a0 = As[kk][ty * 4 + 0];
            float a1 = As[kk][ty * 4 + 1];
            float a2 = As[kk][ty * 4 + 2];
            float a3 = As[kk][ty * 4 + 3];
            fma16(acc, a0, a1, a2, a3, b4);
        }
        __syncthreads();
    }

    float4 bb = *(const float4*)&bias[n0 + tx * 4];
    float* outp = g_qkv + ((size_t)which * NH + head) * (size_t)(SEQ * HD);
    #pragma unroll
    for (int i = 0; i < 4; i++) {
        int m = m0 + ty * 4 + i;
        float4 r;
        r.x = acc[i][0] + bb.x;
        r.y = acc[i][1] + bb.y;
        r.z = acc[i][2] + bb.z;
        r.w = acc[i][3] + bb.w;
        *(float4*)&outp[(size_t)m * HD + tx * 4] = r;
    }
}

// ---------------------------------------------------------------------------
// Kernel 2: flash attention, fp32. Grid: (qtile=64, head=12). Block 256.
// Per block: 64 q rows. Loop 64-key tiles: S=Q·K^T (scale folded into Q),
// online softmax (shfl-xor row reduce over the 16 tx lanes), P overlays K^T
// in smem, O += P·V.  Dynamic smem: Qs 64x64 + Kt/P 64x68 + Vs 64x68 = 50 KB.
// ---------------------------------------------------------------------------
__global__ __launch_bounds__(256) void attn_kernel()
{
    extern __shared__ float sm[];
    float* Qs = sm;                  // [64][64]
    float* Kt = sm + 64 * 64;        // [64][68]  K^T (d-major), later P (row-major)
    float* Vs = Kt + 64 * 68;        // [64][68]

    const int head = blockIdx.y;
    const int q0 = blockIdx.x * 64;
    const float* Qg = g_qkv + ((size_t)0 * NH + head) * (size_t)(SEQ * HD);
    const float* Kg = g_qkv + ((size_t)1 * NH + head) * (size_t)(SEQ * HD);
    const float* Vg = g_qkv + ((size_t)2 * NH + head) * (size_t)(SEQ * HD);
    const int tid = threadIdx.x;
    const int tx = tid & 15, ty = tid >> 4;

    // Load Q tile with 1/sqrt(64) folded in.
    #pragma unroll
    for (int rep = 0; rep < 4; rep++) {
        int idx = rep * 256 + tid;
        int r = idx >> 4, cg = idx & 15;
        float4 v = *(const float4*)&Qg[(size_t)(q0 + r) * HD + cg * 4];
        v.x *= 0.125f; v.y *= 0.125f; v.z *= 0.125f; v.w *= 0.125f;
        *(float4*)&Qs[r * 64 + cg * 4] = v;
    }

    float o[4][4] = {};
    float mi[4], li[4];
    #pragma unroll
    for (int i = 0; i < 4; i++) { mi[i] = -INFINITY; li[i] = 0.f; }

    for (int t0 = 0; t0 < SEQ; t0 += 64) {
        __syncthreads();   // previous iter's P/V reads done (also covers Qs on iter 0)
        #pragma unroll
        for (int rep = 0; rep < 4; rep++) {
            int idx = rep * 256 + tid;
            int r = idx >> 4, cg = idx & 15;
            float4 kv = *(const float4*)&Kg[(size_t)(t0 + r) * HD + cg * 4];
            Kt[(cg * 4 + 0) * 68 + r] = kv.x;
            Kt[(cg * 4 + 1) * 68 + r] = kv.y;
            Kt[(cg * 4 + 2) * 68 + r] = kv.z;
            Kt[(cg * 4 + 3) * 68 + r] = kv.w;
            float4 vv = *(const float4*)&Vg[(size_t)(t0 + r) * HD + cg * 4];
            *(float4*)&Vs[r * 68 + cg * 4] = vv;
        }
        __syncthreads();

        // S = Qs @ Kt   (thread owns rows ty*4..+3, key cols tx*4..+3)
        float s[4][4] = {};
        #pragma unroll 16
        for (int d = 0; d < 64; d++) {
            float4 b4 = *(const float4*)&Kt[d * 68 + tx * 4];
            float a0 = Qs[(ty * 4 + 0) * 64 + d];
            float a1 = Qs[(ty * 4 + 1) * 64 + d];
            float a2 = Qs[(ty * 4 + 2) * 64 + d];
            float a3 = Qs[(ty * 4 + 3) * 64 + d];
            fma16(s, a0, a1, a2, a3, b4);
        }

        // Online softmax per row (reduce across the 16 tx lanes of this ty group).
        #pragma unroll
        for (int i = 0; i < 4; i++) {
            float mx = fmaxf(fmaxf(s[i][0], s[i][1]), fmaxf(s[i][2], s[i][3]));
            #pragma unroll
            for (int off = 8; off > 0; off >>= 1)
                mx = fmaxf(mx, __shfl_xor_sync(0xffffffffu, mx, off));
            float mn = fmaxf(mi[i], mx);
            float sc = __expf(mi[i] - mn);   // 0 on first tile (exp(-inf))
            mi[i] = mn;
            float sum = 0.f;
            #pragma unroll
            for (int j = 0; j < 4; j++) {
                s[i][j] = __expf(s[i][j] - mn);
                sum += s[i][j];
            }
            #pragma unroll
            for (int off = 8; off > 0; off >>= 1)
                sum += __shfl_xor_sync(0xffffffffu, sum, off);
            li[i] = li[i] * sc + sum;
            o[i][0] *= sc; o[i][1] *= sc; o[i][2] *= sc; o[i][3] *= sc;
        }

        __syncthreads();   // everyone done reading Kt as K^T
        #pragma unroll
        for (int i = 0; i < 4; i++)
            *(float4*)&Kt[(ty * 4 + i) * 68 + tx * 4] =
                make_float4(s[i][0], s[i][1], s[i][2], s[i][3]);
        __syncthreads();

        // O += P @ V   (thread owns rows ty*4..+3, dim cols tx*4..+3)
        #pragma unroll 16
        for (int k = 0; k < 64; k++) {
            float4 b4 = *(const float4*)&Vs[k * 68 + tx * 4];
            float a0 = Kt[(ty * 4 + 0) * 68 + k];
            float a1 = Kt[(ty * 4 + 1) * 68 + k];
            float a2 = Kt[(ty * 4 + 2) * 68 + k];
            float a3 = Kt[(ty * 4 + 3) * 68 + k];
            fma16(o, a0, a1, a2, a3, b4);
        }
    }

    float* Og = g_attn + (size_t)head * (size_t)(SEQ * HD);
    #pragma unroll
    for (int i = 0; i < 4; i++) {
        float inv = 1.0f / li[i];
        float4 r = make_float4(o[i][0] * inv, o[i][1] * inv, o[i][2] * inv, o[i][3] * inv);
        *(float4*)&Og[(size_t)(q0 + ty * 4 + i) * HD + tx * 4] = r;
    }
}

// ---------------------------------------------------------------------------
// Kernel 3: output projection. out = concat_heads(g_attn) @ Wo + bo.
// Same GEMM as kernel 1; the A load gathers across heads (k -> head, d).
// ---------------------------------------------------------------------------
__global__ __launch_bounds__(256) void proj_out(
    const float* __restrict__ Wo, const float* __restrict__ bo,
    float* __restrict__ out)
{
    __shared__ float As[16][65];
    __shared__ float Bs[16][64];

    const int n0 = blockIdx.x * 64;
    const int m0 = blockIdx.y * 64;
    const int tid = threadIdx.x;
    const int tx = tid & 15, ty = tid >> 4;
    const int arow = tid >> 2, acg = tid & 3;
    const int brow = tid >> 4, bcg = tid & 15;

    float acc[4][4] = {};

    for (int k0 = 0; k0 < EMB; k0 += 16) {
        int k = k0 + acg * 4;
        int h = k >> 6, d = k & 63;
        float4 av = *(const float4*)&g_attn[((size_t)h * SEQ + (m0 + arow)) * HD + d];
        float4 bw = *(const float4*)&Wo[(size_t)(k0 + brow) * EMB + n0 + bcg * 4];
        As[acg * 4 + 0][arow] = av.x;
        As[acg * 4 + 1][arow] = av.y;
        As[acg * 4 + 2][arow] = av.z;
        As[acg * 4 + 3][arow] = av.w;
        *(float4*)&Bs[brow][bcg * 4] = bw;
        __syncthreads();
        #pragma unroll
        for (int kk = 0; kk < 16; kk++) {
            float4 b4 = *(const float4*)&Bs[kk][tx * 4];
            float a0 = As[kk][ty * 4 + 0];
            float a1 = As[kk][ty * 4 + 1];
            float a2 = As[kk][ty * 4 + 2];
            float a3 = As[kk][ty * 4 + 3];
            fma16(acc, a0, a1, a2, a3, b4);
        }
        __syncthreads();
    }

    float4 bb = *(const float4*)&bo[n0 + tx * 4];
    #pragma unroll
    for (int i = 0; i < 4; i++) {
        int m = m0 + ty * 4 + i;
        float4 r;
        r.x = acc[i][0] + bb.x;
        r.y = acc[i][1] + bb.y;
        r.z = acc[i][2] + bb.z;
        r.w = acc[i][3] + bb.w;
        *(float4*)&out[(size_t)m * EMB + n0 + tx * 4] = r;
    }
}

// ---------------------------------------------------------------------------
// Launch. Input order (metadata): x, Wk, bk, Wq, bq, Wv, bv, Wo, bo.
// ---------------------------------------------------------------------------
extern "C" void kernel_launch(void* const* d_in, const int* in_sizes, int n_in,
                              void* d_out, int out_size)
{
    const float* x  = (const float*)d_in[0];
    const float* Wk = (const float*)d_in[1];
    const float* bk = (const float*)d_in[2];
    const float* Wq = (const float*)d_in[3];
    const float* bq = (const float*)d_in[4];
    const float* Wv = (const float*)d_in[5];
    const float* bv = (const float*)d_in[6];
    const float* Wo = (const float*)d_in[7];
    const float* bo = (const float*)d_in[8];
    float* out = (float*)d_out;

    proj_qkv<<<dim3(NH, SEQ / 64, 3), 256>>>(x, Wq, bq, Wk, bk, Wv, bv);

    int smem = (64 * 64 + 2 * 64 * 68) * (int)sizeof(float);  // 51200 B
    cudaFuncSetAttribute(attn_kernel, cudaFuncAttributeMaxDynamicSharedMemorySize, smem);
    attn_kernel<<<dim3(SEQ / 64, NH), 256, smem>>>();

    proj_out<<<dim3(EMB / 64, SEQ / 64), 256>>>(Wo, bo, out);
}

// round 5
// speedup vs baseline: 2.5303x; 2.5303x over previous
#include <cuda_runtime.h>
#include <math.h>
#include <stdint.h>

#define SEQ 4096
#define EMB 768
#define NH  12
#define HD  64

// Scratch (allocation-free rule: __device__ globals).
__device__ float g_qkv[3 * NH * SEQ * HD];   // [which][head][seq][hd]
__device__ float g_attn[NH * SEQ * HD];      // [head][seq][hd]

// f32 -> tf32 (round-to-nearest) kept in a b32 register / stored as float bits.
__device__ __forceinline__ uint32_t f2tf(float f) {
    uint32_t r;
    asm("cvt.rna.tf32.f32 %0, %1;" : "=r"(r) : "f"(f));
    return r;
}
__device__ __forceinline__ float f2tff(float f) { return __uint_as_float(f2tf(f)); }

// D = A(16x8,tf32) * B(8x8,tf32) + D(16x8,f32), row.col.
__device__ __forceinline__ void mma_tf32(float& c0, float& c1, float& c2, float& c3,
                                         uint32_t a0, uint32_t a1, uint32_t a2, uint32_t a3,
                                         uint32_t b0, uint32_t b1) {
    asm volatile(
        "mma.sync.aligned.m16n8k8.row.col.f32.tf32.tf32.f32 "
        "{%0,%1,%2,%3}, {%4,%5,%6,%7}, {%8,%9}, {%0,%1,%2,%3};"
        : "+f"(c0), "+f"(c1), "+f"(c2), "+f"(c3)
        : "r"(a0), "r"(a1), "r"(a2), "r"(a3), "r"(b0), "r"(b1));
}

// ---------------------------------------------------------------------------
// Kernel 1: QKV projections (tf32 tensor). y = x @ W + b -> g_qkv head-major.
// Grid (head=12, mtile=64, which=3), 128 threads = 4 warps.
// Block tile M=64 (16/warp), N=64 (one head), K-step 16.
// ---------------------------------------------------------------------------
__global__ __launch_bounds__(128) void proj_qkv(
    const float* __restrict__ x,
    const float* __restrict__ Wq, const float* __restrict__ bq,
    const float* __restrict__ Wk, const float* __restrict__ bk,
    const float* __restrict__ Wv, const float* __restrict__ bv)
{
    __shared__ float As[16][68];   // [k][m] (transposed)
    __shared__ float Bs[16][68];   // [k][n]

    const int which = blockIdx.z;
    const float* W    = (which == 0) ? Wq : (which == 1) ? Wk : Wv;
    const float* bias = (which == 0) ? bq : (which == 1) ? bk : bv;
    const int head = blockIdx.x;
    const int n0 = head * 64;
    const int m0 = blockIdx.y * 64;
    const int tid  = threadIdx.x;
    const int lane = tid & 31, w = tid >> 5;
    const int g = lane >> 2, tig = lane & 3;

    float acc[8][4] = {};

    for (int k0 = 0; k0 < EMB; k0 += 16) {
        __syncthreads();
        #pragma unroll
        for (int rep = 0; rep < 2; rep++) {           // X: 64m x 16k, transpose in
            int f = rep * 128 + tid;                  // float4 idx 0..255
            int r = f >> 2;                           // m row 0..63
            int cq = (f & 3) * 4;                     // k col 0,4,8,12
            float4 v = *(const float4*)&x[(size_t)(m0 + r) * EMB + k0 + cq];
            As[cq + 0][r] = f2tff(v.x);
            As[cq + 1][r] = f2tff(v.y);
            As[cq + 2][r] = f2tff(v.z);
            As[cq + 3][r] = f2tff(v.w);
        }
        #pragma unroll
        for (int rep = 0; rep < 2; rep++) {           // W: 16k x 64n
            int f = rep * 128 + tid;
            int r = f >> 4;                           // k 0..15
            int c = (f & 15) * 4;
            float4 v = *(const float4*)&W[(size_t)(k0 + r) * EMB + n0 + c];
            Bs[r][c + 0] = f2tff(v.x);
            Bs[r][c + 1] = f2tff(v.y);
            Bs[r][c + 2] = f2tff(v.z);
            Bs[r][c + 3] = f2tff(v.w);
        }
        __syncthreads();
        #pragma unroll
        for (int kh = 0; kh < 2; kh++) {
            uint32_t a0 = __float_as_uint(As[kh * 8 + tig    ][w * 16 + g]);
            uint32_t a1 = __float_as_uint(As[kh * 8 + tig    ][w * 16 + g + 8]);
            uint32_t a2 = __float_as_uint(As[kh * 8 + tig + 4][w * 16 + g]);
            uint32_t a3 = __float_as_uint(As[kh * 8 + tig + 4][w * 16 + g + 8]);
            #pragma unroll
            for (int n = 0; n < 8; n++) {
                uint32_t b0 = __float_as_uint(Bs[kh * 8 + tig    ][n * 8 + g]);
                uint32_t b1 = __float_as_uint(Bs[kh * 8 + tig + 4][n * 8 + g]);
                mma_tf32(acc[n][0], acc[n][1], acc[n][2], acc[n][3], a0, a1, a2, a3, b0, b1);
            }
        }
    }

    float* outp = g_qkv + ((size_t)which * NH + head) * (size_t)(SEQ * HD);
    const int r0 = m0 + w * 16 + g, r1 = r0 + 8;
    #pragma unroll
    for (int n = 0; n < 8; n++) {
        int cc = n * 8 + 2 * tig;
        float b0 = bias[n0 + cc], b1 = bias[n0 + cc + 1];
        *(float2*)&outp[(size_t)r0 * HD + cc] = make_float2(acc[n][0] + b0, acc[n][1] + b1);
        *(float2*)&outp[(size_t)r1 * HD + cc] = make_float2(acc[n][2] + b0, acc[n][3] + b1);
    }
}

// ---------------------------------------------------------------------------
// Kernel 2: flash attention, tf32 tensor. Grid (qtile=64, head=12), 128 thr.
// Warp tile: 16 q-rows x 64 keys, Q frags register-resident (scale folded).
// K/V tiles (64x64) tf32-rounded in smem (stride 68 -> conflict-free b-frags).
// P re-fragmented via per-warp smem slab. Online softmax in registers.
// ---------------------------------------------------------------------------
__global__ __launch_bounds__(128) void attn_mma()
{
    extern __shared__ float sm[];
    float* Ks = sm;                    // [64][68]
    float* Vs = sm + 64 * 68;          // [64][68]
    float* Ps = Vs + 64 * 68;          // [4][16][68]

    const int head = blockIdx.y;
    const int q0 = blockIdx.x * 64;
    const float* Qg = g_qkv + ((size_t)0 * NH + head) * (size_t)(SEQ * HD);
    const float* Kg = g_qkv + ((size_t)1 * NH + head) * (size_t)(SEQ * HD);
    const float* Vg = g_qkv + ((size_t)2 * NH + head) * (size_t)(SEQ * HD);
    const int tid  = threadIdx.x;
    const int lane = tid & 31, w = tid >> 5;
    const int g = lane >> 2, tig = lane & 3;
    float* Pw = Ps + w * 16 * 68;

    // Q fragments: rows q0 + w*16 + {g, g+8}; cols kc*8 + {tig, tig+4}. 1/8 folded.
    uint32_t qa[8][4];
    {
        const float* qr0 = Qg + (size_t)(q0 + w * 16 + g) * HD;
        const float* qr1 = qr0 + 8 * HD;
        #pragma unroll
        for (int kc = 0; kc < 8; kc++) {
            qa[kc][0] = f2tf(qr0[kc * 8 + tig]     * 0.125f);
            qa[kc][1] = f2tf(qr1[kc * 8 + tig]     * 0.125f);
            qa[kc][2] = f2tf(qr0[kc * 8 + tig + 4] * 0.125f);
            qa[kc][3] = f2tf(qr1[kc * 8 + tig + 4] * 0.125f);
        }
    }

    float o[8][4] = {};
    float m0 = -INFINITY, m1 = -INFINITY, l0 = 0.f, l1 = 0.f;

    for (int t0 = 0; t0 < SEQ; t0 += 64) {
        __syncthreads();                         // prev-iter K/V reads complete
        #pragma unroll
        for (int rep = 0; rep < 8; rep++) {      // K + V tiles (full 64 rows), tf32-rounded
            int f = rep * 128 + tid;             // float4 idx 0..1023
            int r = f >> 4, c4 = (f & 15) * 4;   // r 0..63, c4 0..60
            float4 kv = *(const float4*)&Kg[(size_t)(t0 + r) * HD + c4];
            float4 ks = make_float4(f2tff(kv.x), f2tff(kv.y), f2tff(kv.z), f2tff(kv.w));
            *(float4*)&Ks[r * 68 + c4] = ks;
            float4 vv = *(const float4*)&Vg[(size_t)(t0 + r) * HD + c4];
            float4 vs = make_float4(f2tff(vv.x), f2tff(vv.y), f2tff(vv.z), f2tff(vv.w));
            *(float4*)&Vs[r * 68 + c4] = vs;
        }
        __syncthreads();

        // S = Q * K^T   (warp: 16 x 64)
        float s[8][4] = {};
        #pragma unroll
        for (int kc = 0; kc < 8; kc++) {
            #pragma unroll
            for (int n = 0; n < 8; n++) {
                uint32_t b0 = __float_as_uint(Ks[(n * 8 + g) * 68 + kc * 8 + tig]);
                uint32_t b1 = __float_as_uint(Ks[(n * 8 + g) * 68 + kc * 8 + tig + 4]);
                mma_tf32(s[n][0], s[n][1], s[n][2], s[n][3],
                         qa[kc][0], qa[kc][1], qa[kc][2], qa[kc][3], b0, b1);
            }
        }

        // Online softmax. Thread owns rows g (c0,c1) and g+8 (c2,c3).
        float mx0 = -INFINITY, mx1 = -INFINITY;
        #pragma unroll
        for (int n = 0; n < 8; n++) {
            mx0 = fmaxf(mx0, fmaxf(s[n][0], s[n][1]));
            mx1 = fmaxf(mx1, fmaxf(s[n][2], s[n][3]));
        }
        mx0 = fmaxf(mx0, __shfl_xor_sync(0xffffffffu, mx0, 1));
        mx0 = fmaxf(mx0, __shfl_xor_sync(0xffffffffu, mx0, 2));
        mx1 = fmaxf(mx1, __shfl_xor_sync(0xffffffffu, mx1, 1));
        mx1 = fmaxf(mx1, __shfl_xor_sync(0xffffffffu, mx1, 2));
        float nm0 = fmaxf(m0, mx0), nm1 = fmaxf(m1, mx1);
        float sc0 = __expf(m0 - nm0), sc1 = __expf(m1 - nm1);  // 0 on first tile
        m0 = nm0; m1 = nm1;
        float sum0 = 0.f, sum1 = 0.f;
        #pragma unroll
        for (int n = 0; n < 8; n++) {
            s[n][0] = __expf(s[n][0] - m0); sum0 += s[n][0];
            s[n][1] = __expf(s[n][1] - m0); sum0 += s[n][1];
            s[n][2] = __expf(s[n][2] - m1); sum1 += s[n][2];
            s[n][3] = __expf(s[n][3] - m1); sum1 += s[n][3];
        }
        sum0 += __shfl_xor_sync(0xffffffffu, sum0, 1);
        sum0 += __shfl_xor_sync(0xffffffffu, sum0, 2);
        sum1 += __shfl_xor_sync(0xffffffffu, sum1, 1);
        sum1 += __shfl_xor_sync(0xffffffffu, sum1, 2);
        l0 = l0 * sc0 + sum0;
        l1 = l1 * sc1 + sum1;
        #pragma unroll
        for (int n = 0; n < 8; n++) {
            o[n][0] *= sc0; o[n][1] *= sc0; o[n][2] *= sc1; o[n][3] *= sc1;
        }

        // P: C-fragment layout -> per-warp smem -> A-fragment layout.
        #pragma unroll
        for (int n = 0; n < 8; n++) {
            int cc = n * 8 + 2 * tig;
            *(float2*)&Pw[g * 68 + cc]       = make_float2(f2tff(s[n][0]), f2tff(s[n][1]));
            *(float2*)&Pw[(g + 8) * 68 + cc] = make_float2(f2tff(s[n][2]), f2tff(s[n][3]));
        }
        __syncwarp();

        // O += P * V   (warp: 16 x 64)
        #pragma unroll
        for (int kc = 0; kc < 8; kc++) {
            uint32_t pa0 = __float_as_uint(Pw[g * 68 + kc * 8 + tig]);
            uint32_t pa1 = __float_as_uint(Pw[(g + 8) * 68 + kc * 8 + tig]);
            uint32_t pa2 = __float_as_uint(Pw[g * 68 + kc * 8 + tig + 4]);
            uint32_t pa3 = __float_as_uint(Pw[(g + 8) * 68 + kc * 8 + tig + 4]);
            #pragma unroll
            for (int n = 0; n < 8; n++) {
                uint32_t b0 = __float_as_uint(Vs[(kc * 8 + tig) * 68 + n * 8 + g]);
                uint32_t b1 = __float_as_uint(Vs[(kc * 8 + tig + 4) * 68 + n * 8 + g]);
                mma_tf32(o[n][0], o[n][1], o[n][2], o[n][3], pa0, pa1, pa2, pa3, b0, b1);
            }
        }
        __syncwarp();     // P reads done before next-iter overwrite
    }

    float inv0 = 1.0f / l0, inv1 = 1.0f / l1;
    float* Og = g_attn + (size_t)head * (size_t)(SEQ * HD);
    const int r0 = q0 + w * 16 + g, r1 = r0 + 8;
    #pragma unroll
    for (int n = 0; n < 8; n++) {
        int cc = n * 8 + 2 * tig;
        *(float2*)&Og[(size_t)r0 * HD + cc] = make_float2(o[n][0] * inv0, o[n][1] * inv0);
        *(float2*)&Og[(size_t)r1 * HD + cc] = make_float2(o[n][2] * inv1, o[n][3] * inv1);
    }
}

// ---------------------------------------------------------------------------
// Kernel 3: output projection (tf32 tensor) with head-gather on A.
// out = concat_heads(g_attn) @ Wo + bo. Grid (ntile=12, mtile=64), 128 thr.
// ---------------------------------------------------------------------------
__global__ __launch_bounds__(128) void proj_out(
    const float* __restrict__ Wo, const float* __restrict__ bo,
    float* __restrict__ out)
{
    __shared__ float As[16][68];
    __shared__ float Bs[16][68];

    const int n0 = blockIdx.x * 64;
    const int m0 = blockIdx.y * 64;
    const int tid  = threadIdx.x;
    const int lane = tid & 31, w = tid >> 5;
    const int g = lane >> 2, tig = lane & 3;

    float acc[8][4] = {};

    for (int k0 = 0; k0 < EMB; k0 += 16) {
        __syncthreads();
        #pragma unroll
        for (int rep = 0; rep < 2; rep++) {           // A gather: k -> (head, d)
            int f = rep * 128 + tid;
            int r = f >> 2;
            int cq = (f & 3) * 4;
            int k = k0 + cq;
            int h = k >> 6, d = k & 63;
            float4 v = *(const float4*)&g_attn[((size_t)h * SEQ + (m0 + r)) * HD + d];
            As[cq + 0][r] = f2tff(v.x);
            As[cq + 1][r] = f2tff(v.y);
            As[cq + 2][r] = f2tff(v.z);
            As[cq + 3][r] = f2tff(v.w);
        }
        #pragma unroll
        for (int rep = 0; rep < 2; rep++) {
            int f = rep * 128 + tid;
            int r = f >> 4;
            int c = (f & 15) * 4;
            float4 v = *(const float4*)&Wo[(size_t)(k0 + r) * EMB + n0 + c];
            Bs[r][c + 0] = f2tff(v.x);
            Bs[r][c + 1] = f2tff(v.y);
            Bs[r][c + 2] = f2tff(v.z);
            Bs[r][c + 3] = f2tff(v.w);
        }
        __syncthreads();
        #pragma unroll
        for (int kh = 0; kh < 2; kh++) {
            uint32_t a0 = __float_as_uint(As[kh * 8 + tig    ][w * 16 + g]);
            uint32_t a1 = __float_as_uint(As[kh * 8 + tig    ][w * 16 + g + 8]);
            uint32_t a2 = __float_as_uint(As[kh * 8 + tig + 4][w * 16 + g]);
            uint32_t a3 = __float_as_uint(As[kh * 8 + tig + 4][w * 16 + g + 8]);
            #pragma unroll
            for (int n = 0; n < 8; n++) {
                uint32_t b0 = __float_as_uint(Bs[kh * 8 + tig    ][n * 8 + g]);
                uint32_t b1 = __float_as_uint(Bs[kh * 8 + tig + 4][n * 8 + g]);
                mma_tf32(acc[n][0], acc[n][1], acc[n][2], acc[n][3], a0, a1, a2, a3, b0, b1);
            }
        }
    }

    const int r0 = m0 + w * 16 + g, r1 = r0 + 8;
    #pragma unroll
    for (int n = 0; n < 8; n++) {
        int cc = n0 + n * 8 + 2 * tig;
        float b0 = bo[cc], b1 = bo[cc + 1];
        *(float2*)&out[(size_t)r0 * EMB + cc] = make_float2(acc[n][0] + b0, acc[n][1] + b1);
        *(float2*)&out[(size_t)r1 * EMB + cc] = make_float2(acc[n][2] + b0, acc[n][3] + b1);
    }
}

// ---------------------------------------------------------------------------
// Launch. Input order (metadata): x, Wk, bk, Wq, bq, Wv, bv, Wo, bo.
// ---------------------------------------------------------------------------
extern "C" void kernel_launch(void* const* d_in, const int* in_sizes, int n_in,
                              void* d_out, int out_size)
{
    const float* x  = (const float*)d_in[0];
    const float* Wk = (const float*)d_in[1];
    const float* bk = (const float*)d_in[2];
    const float* Wq = (const float*)d_in[3];
    const float* bq = (const float*)d_in[4];
    const float* Wv = (const float*)d_in[5];
    const float* bv = (const float*)d_in[6];
    const float* Wo = (const float*)d_in[7];
    const float* bo = (const float*)d_in[8];
    float* out = (float*)d_out;

    proj_qkv<<<dim3(NH, SEQ / 64, 3), 128>>>(x, Wq, bq, Wk, bk, Wv, bv);

    int smem = (2 * 64 * 68 + 4 * 16 * 68) * (int)sizeof(float);   // 52224 B
    cudaFuncSetAttribute(attn_mma, cudaFuncAttributeMaxDynamicSharedMemorySize, smem);
    attn_mma<<<dim3(SEQ / 64, NH), 128, smem>>>();

    proj_out<<<dim3(EMB / 64, SEQ / 64), 128>>>(Wo, bo, out);
}

// round 6
// speedup vs baseline: 3.2483x; 1.2838x over previous
#include <cuda_runtime.h>
#include <math.h>
#include <stdint.h>

#define SEQ 4096
#define EMB 768
#define NH  12
#define HD  64

// Scratch (allocation-free rule: __device__ globals).
__device__ float g_qkv[3 * NH * SEQ * HD];   // [which][head][seq][hd]
__device__ float g_attn[NH * SEQ * HD];      // [head][seq][hd]

__device__ __forceinline__ uint32_t f2tf(float f) {
    uint32_t r;
    asm("cvt.rna.tf32.f32 %0, %1;" : "=r"(r) : "f"(f));
    return r;
}
__device__ __forceinline__ float f2tff(float f) { return __uint_as_float(f2tf(f)); }

// pack {hi, lo} floats -> bf16x2
__device__ __forceinline__ uint32_t bf16x2(float hi, float lo) {
    uint32_t d;
    asm("cvt.rn.bf16x2.f32 %0, %1, %2;" : "=r"(d) : "f"(hi), "f"(lo));
    return d;
}

// D += A(16x8,tf32) * B(8x8,tf32), row.col, fp32 acc.
__device__ __forceinline__ void mma_tf32(float* c,
                                         const uint32_t* a,
                                         uint32_t b0, uint32_t b1) {
    asm volatile(
        "mma.sync.aligned.m16n8k8.row.col.f32.tf32.tf32.f32 "
        "{%0,%1,%2,%3}, {%4,%5,%6,%7}, {%8,%9}, {%0,%1,%2,%3};"
        : "+f"(c[0]), "+f"(c[1]), "+f"(c[2]), "+f"(c[3])
        : "r"(a[0]), "r"(a[1]), "r"(a[2]), "r"(a[3]), "r"(b0), "r"(b1));
}

// D += A(16x16,bf16) * B(16x8,bf16), row.col, fp32 acc.
__device__ __forceinline__ void mma_bf16(float* c,
                                         const uint32_t* a,
                                         uint32_t b0, uint32_t b1) {
    asm volatile(
        "mma.sync.aligned.m16n8k16.row.col.f32.bf16.bf16.f32 "
        "{%0,%1,%2,%3}, {%4,%5,%6,%7}, {%8,%9}, {%0,%1,%2,%3};"
        : "+f"(c[0]), "+f"(c[1]), "+f"(c[2]), "+f"(c[3])
        : "r"(a[0]), "r"(a[1]), "r"(a[2]), "r"(a[3]), "r"(b0), "r"(b1));
}

// ---------------------------------------------------------------------------
// Kernel 1: QKV projections. Block 128 thr = 4 warps, tile M=128 x N=64 (one
// head), K-step 32. Warp tile m32n64 (2 m16-subtiles). A stored [m][k] pad 36
// (frag banks 4g+tig, conflict-free), B [k][n] pad 72 (banks 8tig+g, c-free).
// ---------------------------------------------------------------------------
__global__ __launch_bounds__(128) void proj_qkv(
    const float* __restrict__ x,
    const float* __restrict__ Wq, const float* __restrict__ bq,
    const float* __restrict__ Wk, const float* __restrict__ bk,
    const float* __restrict__ Wv, const float* __restrict__ bv)
{
    __shared__ float As[128][36];
    __shared__ float Bs[32][72];

    const int which = blockIdx.z;
    const float* W    = (which == 0) ? Wq : (which == 1) ? Wk : Wv;
    const float* bias = (which == 0) ? bq : (which == 1) ? bk : bv;
    const int head = blockIdx.x;
    const int n0 = head * 64;
    const int m0 = blockIdx.y * 128;
    const int tid  = threadIdx.x;
    const int lane = tid & 31, w = tid >> 5;
    const int g = lane >> 2, tig = lane & 3;

    float acc[2][8][4] = {};

    for (int k0 = 0; k0 < EMB; k0 += 32) {
        __syncthreads();
        #pragma unroll
        for (int rep = 0; rep < 8; rep++) {           // X: 128m x 32k
            int f = rep * 128 + tid;
            int r = f >> 3, cq = (f & 7) * 4;
            float4 v = *(const float4*)&x[(size_t)(m0 + r) * EMB + k0 + cq];
            *(float4*)&As[r][cq] =
                make_float4(f2tff(v.x), f2tff(v.y), f2tff(v.z), f2tff(v.w));
        }
        #pragma unroll
        for (int rep = 0; rep < 4; rep++) {           // W: 32k x 64n
            int f = rep * 128 + tid;
            int r = f >> 4, c = (f & 15) * 4;
            float4 v = *(const float4*)&W[(size_t)(k0 + r) * EMB + n0 + c];
            *(float4*)&Bs[r][c] =
                make_float4(f2tff(v.x), f2tff(v.y), f2tff(v.z), f2tff(v.w));
        }
        __syncthreads();
        #pragma unroll
        for (int kh = 0; kh < 4; kh++) {
            uint32_t a[2][4];
            #pragma unroll
            for (int mt = 0; mt < 2; mt++) {
                int mr = w * 32 + mt * 16 + g;
                a[mt][0] = __float_as_uint(As[mr    ][kh * 8 + tig]);
                a[mt][1] = __float_as_uint(As[mr + 8][kh * 8 + tig]);
                a[mt][2] = __float_as_uint(As[mr    ][kh * 8 + tig + 4]);
                a[mt][3] = __float_as_uint(As[mr + 8][kh * 8 + tig + 4]);
            }
            #pragma unroll
            for (int n = 0; n < 8; n++) {
                uint32_t b0 = __float_as_uint(Bs[kh * 8 + tig    ][n * 8 + g]);
                uint32_t b1 = __float_as_uint(Bs[kh * 8 + tig + 4][n * 8 + g]);
                mma_tf32(acc[0][n], a[0], b0, b1);
                mma_tf32(acc[1][n], a[1], b0, b1);
            }
        }
    }

    float* outp = g_qkv + ((size_t)which * NH + head) * (size_t)(SEQ * HD);
    #pragma unroll
    for (int mt = 0; mt < 2; mt++) {
        const int r0 = m0 + w * 32 + mt * 16 + g, r1 = r0 + 8;
        #pragma unroll
        for (int n = 0; n < 8; n++) {
            int cc = n * 8 + 2 * tig;
            float b0 = bias[n0 + cc], b1 = bias[n0 + cc + 1];
            *(float2*)&outp[(size_t)r0 * HD + cc] =
                make_float2(acc[mt][n][0] + b0, acc[mt][n][1] + b1);
            *(float2*)&outp[(size_t)r1 * HD + cc] =
                make_float2(acc[mt][n][2] + b0, acc[mt][n][3] + b1);
        }
    }
}

// ---------------------------------------------------------------------------
// Kernel 2: flash attention. Block 128 thr = 4 warps, 128 q-rows (warp m32 =
// two m16-subtiles). QK^T in tf32 (K in smem [key][68], b-frag banks 4g+tig).
// P·V in bf16 m16n8k16: P packed straight from S C-frags (no smem round trip),
// V transposed bf16-pairs in smem [hd][36 words] (b-frag banks 4g+tig).
// ---------------------------------------------------------------------------
__global__ __launch_bounds__(128) void attn_mma()
{
    __shared__ float    Ks[64][68];
    __shared__ uint32_t Vt[64][36];    // [hd][key/2]: lo = even key, hi = odd

    const int head = blockIdx.y;
    const int q0 = blockIdx.x * 128;
    const float* Qg = g_qkv + ((size_t)0 * NH + head) * (size_t)(SEQ * HD);
    const float* Kg = g_qkv + ((size_t)1 * NH + head) * (size_t)(SEQ * HD);
    const float* Vg = g_qkv + ((size_t)2 * NH + head) * (size_t)(SEQ * HD);
    const int tid  = threadIdx.x;
    const int lane = tid & 31, w = tid >> 5;
    const int g = lane >> 2, tig = lane & 3;

    // Q fragments for both m16-subtiles, 1/8 scale folded in.
    uint32_t qa[2][8][4];
    #pragma unroll
    for (int mt = 0; mt < 2; mt++) {
        const float* qr0 = Qg + (size_t)(q0 + w * 32 + mt * 16 + g) * HD;
        const float* qr1 = qr0 + 8 * HD;
        #pragma unroll
        for (int kc = 0; kc < 8; kc++) {
            qa[mt][kc][0] = f2tf(qr0[kc * 8 + tig]     * 0.125f);
            qa[mt][kc][1] = f2tf(qr1[kc * 8 + tig]     * 0.125f);
            qa[mt][kc][2] = f2tf(qr0[kc * 8 + tig + 4] * 0.125f);
            qa[mt][kc][3] = f2tf(qr1[kc * 8 + tig + 4] * 0.125f);
        }
    }

    float o[2][8][4] = {};
    float mi[2][2], li[2][2];
    #pragma unroll
    for (int mt = 0; mt < 2; mt++) {
        mi[mt][0] = -INFINITY; mi[mt][1] = -INFINITY;
        li[mt][0] = 0.f;       li[mt][1] = 0.f;
    }

    for (int t0 = 0; t0 < SEQ; t0 += 64) {
        __syncthreads();                       // prev-iter Ks/Vt reads done
        #pragma unroll
        for (int rep = 0; rep < 8; rep++) {
            int f = rep * 128 + tid;
            int r = f >> 4, c4 = (f & 15) * 4;   // r: key pair (r0 even)
            float4 kv = *(const float4*)&Kg[(size_t)(t0 + r) * HD + c4];
            *(float4*)&Ks[r][c4] =
                make_float4(f2tff(kv.x), f2tff(kv.y), f2tff(kv.z), f2tff(kv.w));
            float4 vv = *(const float4*)&Vg[(size_t)(t0 + r) * HD + c4];
            uint32_t p0 = bf16x2(vv.y, vv.x);    // hd c4+1 | c4
            uint32_t p1 = bf16x2(vv.w, vv.z);    // hd c4+3 | c4+2
            uint32_t s0 = __shfl_xor_sync(0xffffffffu, p0, 16);
            uint32_t s1 = __shfl_xor_sync(0xffffffffu, p1, 16);
            int kw = r >> 1;
            if (lane < 16) {                     // my key even, partner odd
                Vt[c4 + 0][kw] = __byte_perm(p0, s0, 0x5410);
                Vt[c4 + 1][kw] = __byte_perm(p0, s0, 0x7632);
            } else {                             // my key odd, partner even
                Vt[c4 + 2][kw] = __byte_perm(s1, p1, 0x5410);
                Vt[c4 + 3][kw] = __byte_perm(s1, p1, 0x7632);
            }
        }
        __syncthreads();

        // S = Q * K^T (both subtiles share each K b-frag load)
        float s[2][8][4] = {};
        #pragma unroll
        for (int kc = 0; kc < 8; kc++) {
            #pragma unroll
            for (int n = 0; n < 8; n++) {
                uint32_t b0 = __float_as_uint(Ks[n * 8 + g][kc * 8 + tig]);
                uint32_t b1 = __float_as_uint(Ks[n * 8 + g][kc * 8 + tig + 4]);
                mma_tf32(s[0][n], qa[0][kc], b0, b1);
                mma_tf32(s[1][n], qa[1][kc], b0, b1);
            }
        }

        // Online softmax per subtile (row halves g and g+8).
        #pragma unroll
        for (int mt = 0; mt < 2; mt++) {
            float mx0 = -INFINITY, mx1 = -INFINITY;
            #pragma unroll
            for (int n = 0; n < 8; n++) {
                mx0 = fmaxf(mx0, fmaxf(s[mt][n][0], s[mt][n][1]));
                mx1 = fmaxf(mx1, fmaxf(s[mt][n][2], s[mt][n][3]));
            }
            mx0 = fmaxf(mx0, __shfl_xor_sync(0xffffffffu, mx0, 1));
            mx0 = fmaxf(mx0, __shfl_xor_sync(0xffffffffu, mx0, 2));
            mx1 = fmaxf(mx1, __shfl_xor_sync(0xffffffffu, mx1, 1));
            mx1 = fmaxf(mx1, __shfl_xor_sync(0xffffffffu, mx1, 2));
            float nm0 = fmaxf(mi[mt][0], mx0), nm1 = fmaxf(mi[mt][1], mx1);
            float sc0 = __expf(mi[mt][0] - nm0), sc1 = __expf(mi[mt][1] - nm1);
            mi[mt][0] = nm0; mi[mt][1] = nm1;
            float sum0 = 0.f, sum1 = 0.f;
            #pragma unroll
            for (int n = 0; n < 8; n++) {
                s[mt][n][0] = __expf(s[mt][n][0] - nm0); sum0 += s[mt][n][0];
                s[mt][n][1] = __expf(s[mt][n][1] - nm0); sum0 += s[mt][n][1];
                s[mt][n][2] = __expf(s[mt][n][2] - nm1); sum1 += s[mt][n][2];
                s[mt][n][3] = __expf(s[mt][n][3] - nm1); sum1 += s[mt][n][3];
            }
            sum0 += __shfl_xor_sync(0xffffffffu, sum0, 1);
            sum0 += __shfl_xor_sync(0xffffffffu, sum0, 2);
            sum1 += __shfl_xor_sync(0xffffffffu, sum1, 1);
            sum1 += __shfl_xor_sync(0xffffffffu, sum1, 2);
            li[mt][0] = li[mt][0] * sc0 + sum0;
            li[mt][1] = li[mt][1] * sc1 + sum1;
            #pragma unroll
            for (int n = 0; n < 8; n++) {
                o[mt][n][0] *= sc0; o[mt][n][1] *= sc0;
                o[mt][n][2] *= sc1; o[mt][n][3] *= sc1;
            }
        }

        // P: S C-frags -> bf16 A-frags (register-only, no smem).
        uint32_t pk[2][4][4];
        #pragma unroll
        for (int mt = 0; mt < 2; mt++)
            #pragma unroll
            for (int kc2 = 0; kc2 < 4; kc2++) {
                pk[mt][kc2][0] = bf16x2(s[mt][2*kc2  ][1], s[mt][2*kc2  ][0]);
                pk[mt][kc2][1] = bf16x2(s[mt][2*kc2  ][3], s[mt][2*kc2  ][2]);
                pk[mt][kc2][2] = bf16x2(s[mt][2*kc2+1][1], s[mt][2*kc2+1][0]);
                pk[mt][kc2][3] = bf16x2(s[mt][2*kc2+1][3], s[mt][2*kc2+1][2]);
            }

        // O += P * V (bf16 k16; V b-frags shared across subtiles)
        #pragma unroll
        for (int kc2 = 0; kc2 < 4; kc2++) {
            #pragma unroll
            for (int n = 0; n < 8; n++) {
                uint32_t b0 = Vt[n * 8 + g][kc2 * 8 + tig];
                uint32_t b1 = Vt[n * 8 + g][kc2 * 8 + tig + 4];
                mma_bf16(o[0][n], pk[0][kc2], b0, b1);
                mma_bf16(o[1][n], pk[1][kc2], b0, b1);
            }
        }
    }

    float* Og = g_attn + (size_t)head * (size_t)(SEQ * HD);
    #pragma unroll
    for (int mt = 0; mt < 2; mt++) {
        float inv0 = 1.0f / li[mt][0], inv1 = 1.0f / li[mt][1];
        const int r0 = q0 + w * 32 + mt * 16 + g, r1 = r0 + 8;
        #pragma unroll
        for (int n = 0; n < 8; n++) {
            int cc = n * 8 + 2 * tig;
            *(float2*)&Og[(size_t)r0 * HD + cc] =
                make_float2(o[mt][n][0] * inv0, o[mt][n][1] * inv0);
            *(float2*)&Og[(size_t)r1 * HD + cc] =
                make_float2(o[mt][n][2] * inv1, o[mt][n][3] * inv1);
        }
    }
}

// ---------------------------------------------------------------------------
// Kernel 3: output projection, same tiling as kernel 1; A gathers across heads.
// ---------------------------------------------------------------------------
__global__ __launch_bounds__(128) void proj_out(
    const float* __restrict__ Wo, const float* __restrict__ bo,
    float* __restrict__ out)
{
    __shared__ float As[128][36];
    __shared__ float Bs[32][72];

    const int n0 = blockIdx.x * 64;
    const int m0 = blockIdx.y * 128;
    const int tid  = threadIdx.x;
    const int lane = tid & 31, w = tid >> 5;
    const int g = lane >> 2, tig = lane & 3;

    float acc[2][8][4] = {};

    for (int k0 = 0; k0 < EMB; k0 += 32) {
        const int h = k0 >> 6, d0 = k0 & 63;      // 32-chunk within one head
        __syncthreads();
        #pragma unroll
        for (int rep = 0; rep < 8; rep++) {
            int f = rep * 128 + tid;
            int r = f >> 3, cq = (f & 7) * 4;
            float4 v = *(const float4*)
                &g_attn[((size_t)h * SEQ + m0 + r) * HD + d0 + cq];
            *(float4*)&As[r][cq] =
                make_float4(f2tff(v.x), f2tff(v.y), f2tff(v.z), f2tff(v.w));
        }
        #pragma unroll
        for (int rep = 0; rep < 4; rep++) {
            int f = rep * 128 + tid;
            int r = f >> 4, c = (f & 15) * 4;
            float4 v = *(const float4*)&Wo[(size_t)(k0 + r) * EMB + n0 + c];
            *(float4*)&Bs[r][c] =
                make_float4(f2tff(v.x), f2tff(v.y), f2tff(v.z), f2tff(v.w));
        }
        __syncthreads();
        #pragma unroll
        for (int kh = 0; kh < 4; kh++) {
            uint32_t a[2][4];
            #pragma unroll
            for (int mt = 0; mt < 2; mt++) {
                int mr = w * 32 + mt * 16 + g;
                a[mt][0] = __float_as_uint(As[mr    ][kh * 8 + tig]);
                a[mt][1] = __float_as_uint(As[mr + 8][kh * 8 + tig]);
                a[mt][2] = __float_as_uint(As[mr    ][kh * 8 + tig + 4]);
                a[mt][3] = __float_as_uint(As[mr + 8][kh * 8 + tig + 4]);
            }
            #pragma unroll
            for (int n = 0; n < 8; n++) {
                uint32_t b0 = __float_as_uint(Bs[kh * 8 + tig    ][n * 8 + g]);
                uint32_t b1 = __float_as_uint(Bs[kh * 8 + tig + 4][n * 8 + g]);
                mma_tf32(acc[0][n], a[0], b0, b1);
                mma_tf32(acc[1][n], a[1], b0, b1);
            }
        }
    }

    #pragma unroll
    for (int mt = 0; mt < 2; mt++) {
        const int r0 = m0 + w * 32 + mt * 16 + g, r1 = r0 + 8;
        #pragma unroll
        for (int n = 0; n < 8; n++) {
            int cc = n0 + n * 8 + 2 * tig;
            float b0 = bo[cc], b1 = bo[cc + 1];
            *(float2*)&out[(size_t)r0 * EMB + cc] =
                make_float2(acc[mt][n][0] + b0, acc[mt][n][1] + b1);
            *(float2*)&out[(size_t)r1 * EMB + cc] =
                make_float2(acc[mt][n][2] + b0, acc[mt][n][3] + b1);
        }
    }
}

// ---------------------------------------------------------------------------
// Launch. Input order (metadata): x, Wk, bk, Wq, bq, Wv, bv, Wo, bo.
// ---------------------------------------------------------------------------
extern "C" void kernel_launch(void* const* d_in, const int* in_sizes, int n_in,
                              void* d_out, int out_size)
{
    const float* x  = (const float*)d_in[0];
    const float* Wk = (const float*)d_in[1];
    const float* bk = (const float*)d_in[2];
    const float* Wq = (const float*)d_in[3];
    const float* bq = (const float*)d_in[4];
    const float* Wv = (const float*)d_in[5];
    const float* bv = (const float*)d_in[6];
    const float* Wo = (const float*)d_in[7];
    const float* bo = (const float*)d_in[8];
    float* out = (float*)d_out;

    proj_qkv<<<dim3(NH, SEQ / 128, 3), 128>>>(x, Wq, bq, Wk, bk, Wv, bv);
    attn_mma<<<dim3(SEQ / 128, NH), 128>>>();
    proj_out<<<dim3(EMB / 64, SEQ / 128), 128>>>(Wo, bo, out);
}

// round 7
// speedup vs baseline: 3.3148x; 1.0205x over previous
#include <cuda_runtime.h>
#include <math.h>
#include <stdint.h>

#define SEQ 4096
#define EMB 768
#define NH  12
#define HD  64

// Scratch (allocation-free rule: __device__ globals).
__device__ float g_qkv[3 * NH * SEQ * HD];   // [which][head][seq][hd]
__device__ float g_attn[NH * SEQ * HD];      // [head][seq][hd]

__device__ __forceinline__ uint32_t f2tf(float f) {
    uint32_t r;
    asm("cvt.rna.tf32.f32 %0, %1;" : "=r"(r) : "f"(f));
    return r;
}
__device__ __forceinline__ float f2tff(float f) { return __uint_as_float(f2tf(f)); }

// pack {hi, lo} floats -> bf16x2
__device__ __forceinline__ uint32_t bf16x2(float hi, float lo) {
    uint32_t d;
    asm("cvt.rn.bf16x2.f32 %0, %1, %2;" : "=r"(d) : "f"(hi), "f"(lo));
    return d;
}

// D += A(16x8,tf32) * B(8x8,tf32), row.col, fp32 acc.
__device__ __forceinline__ void mma_tf32(float* c,
                                         const uint32_t* a,
                                         uint32_t b0, uint32_t b1) {
    asm volatile(
        "mma.sync.aligned.m16n8k8.row.col.f32.tf32.tf32.f32 "
        "{%0,%1,%2,%3}, {%4,%5,%6,%7}, {%8,%9}, {%0,%1,%2,%3};"
        : "+f"(c[0]), "+f"(c[1]), "+f"(c[2]), "+f"(c[3])
        : "r"(a[0]), "r"(a[1]), "r"(a[2]), "r"(a[3]), "r"(b0), "r"(b1));
}

// D += A(16x16,bf16) * B(16x8,bf16), row.col, fp32 acc.
__device__ __forceinline__ void mma_bf16(float* c,
                                         const uint32_t* a,
                                         uint32_t b0, uint32_t b1) {
    asm volatile(
        "mma.sync.aligned.m16n8k16.row.col.f32.bf16.bf16.f32 "
        "{%0,%1,%2,%3}, {%4,%5,%6,%7}, {%8,%9}, {%0,%1,%2,%3};"
        : "+f"(c[0]), "+f"(c[1]), "+f"(c[2]), "+f"(c[3])
        : "r"(a[0]), "r"(a[1]), "r"(a[2]), "r"(a[3]), "r"(b0), "r"(b1));
}

// ---------------------------------------------------------------------------
// Kernel 1: QKV projections (unchanged from R6). Block 128 thr, tile 128x64,
// K-step 32, warp m32n64. Conflict-free padded smem.
// ---------------------------------------------------------------------------
__global__ __launch_bounds__(128) void proj_qkv(
    const float* __restrict__ x,
    const float* __restrict__ Wq, const float* __restrict__ bq,
    const float* __restrict__ Wk, const float* __restrict__ bk,
    const float* __restrict__ Wv, const float* __restrict__ bv)
{
    __shared__ float As[128][36];
    __shared__ float Bs[32][72];

    const int which = blockIdx.z;
    const float* W    = (which == 0) ? Wq : (which == 1) ? Wk : Wv;
    const float* bias = (which == 0) ? bq : (which == 1) ? bk : bv;
    const int head = blockIdx.x;
    const int n0 = head * 64;
    const int m0 = blockIdx.y * 128;
    const int tid  = threadIdx.x;
    const int lane = tid & 31, w = tid >> 5;
    const int g = lane >> 2, tig = lane & 3;

    float acc[2][8][4] = {};

    for (int k0 = 0; k0 < EMB; k0 += 32) {
        __syncthreads();
        #pragma unroll
        for (int rep = 0; rep < 8; rep++) {           // X: 128m x 32k
            int f = rep * 128 + tid;
            int r = f >> 3, cq = (f & 7) * 4;
            float4 v = *(const float4*)&x[(size_t)(m0 + r) * EMB + k0 + cq];
            *(float4*)&As[r][cq] =
                make_float4(f2tff(v.x), f2tff(v.y), f2tff(v.z), f2tff(v.w));
        }
        #pragma unroll
        for (int rep = 0; rep < 4; rep++) {           // W: 32k x 64n
            int f = rep * 128 + tid;
            int r = f >> 4, c = (f & 15) * 4;
            float4 v = *(const float4*)&W[(size_t)(k0 + r) * EMB + n0 + c];
            *(float4*)&Bs[r][c] =
                make_float4(f2tff(v.x), f2tff(v.y), f2tff(v.z), f2tff(v.w));
        }
        __syncthreads();
        #pragma unroll
        for (int kh = 0; kh < 4; kh++) {
            uint32_t a[2][4];
            #pragma unroll
            for (int mt = 0; mt < 2; mt++) {
                int mr = w * 32 + mt * 16 + g;
                a[mt][0] = __float_as_uint(As[mr    ][kh * 8 + tig]);
                a[mt][1] = __float_as_uint(As[mr + 8][kh * 8 + tig]);
                a[mt][2] = __float_as_uint(As[mr    ][kh * 8 + tig + 4]);
                a[mt][3] = __float_as_uint(As[mr + 8][kh * 8 + tig + 4]);
            }
            #pragma unroll
            for (int n = 0; n < 8; n++) {
                uint32_t b0 = __float_as_uint(Bs[kh * 8 + tig    ][n * 8 + g]);
                uint32_t b1 = __float_as_uint(Bs[kh * 8 + tig + 4][n * 8 + g]);
                mma_tf32(acc[0][n], a[0], b0, b1);
                mma_tf32(acc[1][n], a[1], b0, b1);
            }
        }
    }

    float* outp = g_qkv + ((size_t)which * NH + head) * (size_t)(SEQ * HD);
    #pragma unroll
    for (int mt = 0; mt < 2; mt++) {
        const int r0 = m0 + w * 32 + mt * 16 + g, r1 = r0 + 8;
        #pragma unroll
        for (int n = 0; n < 8; n++) {
            int cc = n * 8 + 2 * tig;
            float b0 = bias[n0 + cc], b1 = bias[n0 + cc + 1];
            *(float2*)&outp[(size_t)r0 * HD + cc] =
                make_float2(acc[mt][n][0] + b0, acc[mt][n][1] + b1);
            *(float2*)&outp[(size_t)r1 * HD + cc] =
                make_float2(acc[mt][n][2] + b0, acc[mt][n][3] + b1);
        }
    }
}

// ---------------------------------------------------------------------------
// Kernel 2: flash attention. Block 128 thr = 4 warps, 128 q-rows, warp m32.
// R7 change: each 64-key tile processed as two 32-key halves so the S
// accumulator is [2][4][4] (32 regs) instead of [2][8][4] (64). Peak live
// registers drop below the spill cliff; 2 CTAs/SM. Same math (online softmax
// applied per half), same mma count.
// ---------------------------------------------------------------------------
__global__ __launch_bounds__(128) void attn_mma()
{
    __shared__ float    Ks[64][68];
    __shared__ uint32_t Vt[64][36];    // [hd][key/2]: lo = even key, hi = odd

    const int head = blockIdx.y;
    const int q0 = blockIdx.x * 128;
    const float* Qg = g_qkv + ((size_t)0 * NH + head) * (size_t)(SEQ * HD);
    const float* Kg = g_qkv + ((size_t)1 * NH + head) * (size_t)(SEQ * HD);
    const float* Vg = g_qkv + ((size_t)2 * NH + head) * (size_t)(SEQ * HD);
    const int tid  = threadIdx.x;
    const int lane = tid & 31, w = tid >> 5;
    const int g = lane >> 2, tig = lane & 3;

    // Q fragments for both m16-subtiles, 1/8 scale folded in. (64 regs)
    uint32_t qa[2][8][4];
    #pragma unroll
    for (int mt = 0; mt < 2; mt++) {
        const float* qr0 = Qg + (size_t)(q0 + w * 32 + mt * 16 + g) * HD;
        const float* qr1 = qr0 + 8 * HD;
        #pragma unroll
        for (int kc = 0; kc < 8; kc++) {
            qa[mt][kc][0] = f2tf(qr0[kc * 8 + tig]     * 0.125f);
            qa[mt][kc][1] = f2tf(qr1[kc * 8 + tig]     * 0.125f);
            qa[mt][kc][2] = f2tf(qr0[kc * 8 + tig + 4] * 0.125f);
            qa[mt][kc][3] = f2tf(qr1[kc * 8 + tig + 4] * 0.125f);
        }
    }

    float o[2][8][4] = {};                               // 64 regs
    float mi[2][2], li[2][2];
    #pragma unroll
    for (int mt = 0; mt < 2; mt++) {
        mi[mt][0] = -INFINITY; mi[mt][1] = -INFINITY;
        li[mt][0] = 0.f;       li[mt][1] = 0.f;
    }

    for (int t0 = 0; t0 < SEQ; t0 += 64) {
        __syncthreads();                       // prev-iter Ks/Vt reads done
        #pragma unroll
        for (int rep = 0; rep < 8; rep++) {
            int f = rep * 128 + tid;
            int r = f >> 4, c4 = (f & 15) * 4;   // r = key row
            float4 kv = *(const float4*)&Kg[(size_t)(t0 + r) * HD + c4];
            *(float4*)&Ks[r][c4] =
                make_float4(f2tff(kv.x), f2tff(kv.y), f2tff(kv.z), f2tff(kv.w));
            float4 vv = *(const float4*)&Vg[(size_t)(t0 + r) * HD + c4];
            uint32_t p0 = bf16x2(vv.y, vv.x);    // hd c4+1 | c4
            uint32_t p1 = bf16x2(vv.w, vv.z);    // hd c4+3 | c4+2
            uint32_t s0 = __shfl_xor_sync(0xffffffffu, p0, 16);
            uint32_t s1 = __shfl_xor_sync(0xffffffffu, p1, 16);
            int kw = r >> 1;
            if (lane < 16) {                     // my key even, partner odd
                Vt[c4 + 0][kw] = __byte_perm(p0, s0, 0x5410);
                Vt[c4 + 1][kw] = __byte_perm(p0, s0, 0x7632);
            } else {                             // my key odd, partner even
                Vt[c4 + 2][kw] = __byte_perm(s1, p1, 0x5410);
                Vt[c4 + 3][kw] = __byte_perm(s1, p1, 0x7632);
            }
        }
        __syncthreads();

        #pragma unroll
        for (int h = 0; h < 2; h++) {            // two 32-key halves
            // S = Q * K^T for this half (keys h*32 .. h*32+31)
            float s[2][4][4] = {};               // 32 regs
            #pragma unroll
            for (int kc = 0; kc < 8; kc++) {
                #pragma unroll
                for (int n = 0; n < 4; n++) {
                    int kr = h * 32 + n * 8 + g;
                    uint32_t b0 = __float_as_uint(Ks[kr][kc * 8 + tig]);
                    uint32_t b1 = __float_as_uint(Ks[kr][kc * 8 + tig + 4]);
                    mma_tf32(s[0][n], qa[0][kc], b0, b1);
                    mma_tf32(s[1][n], qa[1][kc], b0, b1);
                }
            }

            // Online softmax update (per subtile; row halves g and g+8).
            #pragma unroll
            for (int mt = 0; mt < 2; mt++) {
                float mx0 = -INFINITY, mx1 = -INFINITY;
                #pragma unroll
                for (int n = 0; n < 4; n++) {
                    mx0 = fmaxf(mx0, fmaxf(s[mt][n][0], s[mt][n][1]));
                    mx1 = fmaxf(mx1, fmaxf(s[mt][n][2], s[mt][n][3]));
                }
                mx0 = fmaxf(mx0, __shfl_xor_sync(0xffffffffu, mx0, 1));
                mx0 = fmaxf(mx0, __shfl_xor_sync(0xffffffffu, mx0, 2));
                mx1 = fmaxf(mx1, __shfl_xor_sync(0xffffffffu, mx1, 1));
                mx1 = fmaxf(mx1, __shfl_xor_sync(0xffffffffu, mx1, 2));
                float nm0 = fmaxf(mi[mt][0], mx0), nm1 = fmaxf(mi[mt][1], mx1);
                float sc0 = __expf(mi[mt][0] - nm0), sc1 = __expf(mi[mt][1] - nm1);
                mi[mt][0] = nm0; mi[mt][1] = nm1;
                float sum0 = 0.f, sum1 = 0.f;
                #pragma unroll
                for (int n = 0; n < 4; n++) {
                    s[mt][n][0] = __expf(s[mt][n][0] - nm0); sum0 += s[mt][n][0];
                    s[mt][n][1] = __expf(s[mt][n][1] - nm0); sum0 += s[mt][n][1];
                    s[mt][n][2] = __expf(s[mt][n][2] - nm1); sum1 += s[mt][n][2];
                    s[mt][n][3] = __expf(s[mt][n][3] - nm1); sum1 += s[mt][n][3];
                }
                sum0 += __shfl_xor_sync(0xffffffffu, sum0, 1);
                sum0 += __shfl_xor_sync(0xffffffffu, sum0, 2);
                sum1 += __shfl_xor_sync(0xffffffffu, sum1, 1);
                sum1 += __shfl_xor_sync(0xffffffffu, sum1, 2);
                li[mt][0] = li[mt][0] * sc0 + sum0;
                li[mt][1] = li[mt][1] * sc1 + sum1;
                #pragma unroll
                for (int n = 0; n < 8; n++) {
                    o[mt][n][0] *= sc0; o[mt][n][1] *= sc0;
                    o[mt][n][2] *= sc1; o[mt][n][3] *= sc1;
                }
            }

            // P: S C-frags -> bf16 A-frags (register-only). 16 regs.
            uint32_t pk[2][2][4];
            #pragma unroll
            for (int mt = 0; mt < 2; mt++)
                #pragma unroll
                for (int kc2 = 0; kc2 < 2; kc2++) {
                    pk[mt][kc2][0] = bf16x2(s[mt][2*kc2  ][1], s[mt][2*kc2  ][0]);
                    pk[mt][kc2][1] = bf16x2(s[mt][2*kc2  ][3], s[mt][2*kc2  ][2]);
                    pk[mt][kc2][2] = bf16x2(s[mt][2*kc2+1][1], s[mt][2*kc2+1][0]);
                    pk[mt][kc2][3] = bf16x2(s[mt][2*kc2+1][3], s[mt][2*kc2+1][2]);
                }

            // O += P * V for this half (bf16 k16; V b-frags shared across mt)
            #pragma unroll
            for (int kc2 = 0; kc2 < 2; kc2++) {
                #pragma unroll
                for (int n = 0; n < 8; n++) {
                    uint32_t b0 = Vt[n * 8 + g][h * 16 + kc2 * 8 + tig];
                    uint32_t b1 = Vt[n * 8 + g][h * 16 + kc2 * 8 + tig + 4];
                    mma_bf16(o[0][n], pk[0][kc2], b0, b1);
                    mma_bf16(o[1][n], pk[1][kc2], b0, b1);
                }
            }
        }
    }

    float* Og = g_attn + (size_t)head * (size_t)(SEQ * HD);
    #pragma unroll
    for (int mt = 0; mt < 2; mt++) {
        float inv0 = 1.0f / li[mt][0], inv1 = 1.0f / li[mt][1];
        const int r0 = q0 + w * 32 + mt * 16 + g, r1 = r0 + 8;
        #pragma unroll
        for (int n = 0; n < 8; n++) {
            int cc = n * 8 + 2 * tig;
            *(float2*)&Og[(size_t)r0 * HD + cc] =
                make_float2(o[mt][n][0] * inv0, o[mt][n][1] * inv0);
            *(float2*)&Og[(size_t)r1 * HD + cc] =
                make_float2(o[mt][n][2] * inv1, o[mt][n][3] * inv1);
        }
    }
}

// ---------------------------------------------------------------------------
// Kernel 3: output projection (unchanged from R6).
// ---------------------------------------------------------------------------
__global__ __launch_bounds__(128) void proj_out(
    const float* __restrict__ Wo, const float* __restrict__ bo,
    float* __restrict__ out)
{
    __shared__ float As[128][36];
    __shared__ float Bs[32][72];

    const int n0 = blockIdx.x * 64;
    const int m0 = blockIdx.y * 128;
    const int tid  = threadIdx.x;
    const int lane = tid & 31, w = tid >> 5;
    const int g = lane >> 2, tig = lane & 3;

    float acc[2][8][4] = {};

    for (int k0 = 0; k0 < EMB; k0 += 32) {
        const int h = k0 >> 6, d0 = k0 & 63;
        __syncthreads();
        #pragma unroll
        for (int rep = 0; rep < 8; rep++) {
            int f = rep * 128 + tid;
            int r = f >> 3, cq = (f & 7) * 4;
            float4 v = *(const float4*)
                &g_attn[((size_t)h * SEQ + m0 + r) * HD + d0 + cq];
            *(float4*)&As[r][cq] =
                make_float4(f2tff(v.x), f2tff(v.y), f2tff(v.z), f2tff(v.w));
        }
        #pragma unroll
        for (int rep = 0; rep < 4; rep++) {
            int f = rep * 128 + tid;
            int r = f >> 4, c = (f & 15) * 4;
            float4 v = *(const float4*)&Wo[(size_t)(k0 + r) * EMB + n0 + c];
            *(float4*)&Bs[r][c] =
                make_float4(f2tff(v.x), f2tff(v.y), f2tff(v.z), f2tff(v.w));
        }
        __syncthreads();
        #pragma unroll
        for (int kh = 0; kh < 4; kh++) {
            uint32_t a[2][4];
            #pragma unroll
            for (int mt = 0; mt < 2; mt++) {
                int mr = w * 32 + mt * 16 + g;
                a[mt][0] = __float_as_uint(As[mr    ][kh * 8 + tig]);
                a[mt][1] = __float_as_uint(As[mr + 8][kh * 8 + tig]);
                a[mt][2] = __float_as_uint(As[mr    ][kh * 8 + tig + 4]);
                a[mt][3] = __float_as_uint(As[mr + 8][kh * 8 + tig + 4]);
            }
            #pragma unroll
            for (int n = 0; n < 8; n++) {
                uint32_t b0 = __float_as_uint(Bs[kh * 8 + tig    ][n * 8 + g]);
                uint32_t b1 = __float_as_uint(Bs[kh * 8 + tig + 4][n * 8 + g]);
                mma_tf32(acc[0][n], a[0], b0, b1);
                mma_tf32(acc[1][n], a[1], b0, b1);
            }
        }
    }

    #pragma unroll
    for (int mt = 0; mt < 2; mt++) {
        const int r0 = m0 + w * 32 + mt * 16 + g, r1 = r0 + 8;
        #pragma unroll
        for (int n = 0; n < 8; n++) {
            int cc = n0 + n * 8 + 2 * tig;
            float b0 = bo[cc], b1 = bo[cc + 1];
            *(float2*)&out[(size_t)r0 * EMB + cc] =
                make_float2(acc[mt][n][0] + b0, acc[mt][n][1] + b1);
            *(float2*)&out[(size_t)r1 * EMB + cc] =
                make_float2(acc[mt][n][2] + b0, acc[mt][n][3] + b1);
        }
    }
}

// ---------------------------------------------------------------------------
// Launch. Input order (metadata): x, Wk, bk, Wq, bq, Wv, bv, Wo, bo.
// ---------------------------------------------------------------------------
extern "C" void kernel_launch(void* const* d_in, const int* in_sizes, int n_in,
                              void* d_out, int out_size)
{
    const float* x  = (const float*)d_in[0];
    const float* Wk = (const float*)d_in[1];
    const float* bk = (const float*)d_in[2];
    const float* Wq = (const float*)d_in[3];
    const float* bq = (const float*)d_in[4];
    const float* Wv = (const float*)d_in[5];
    const float* bv = (const float*)d_in[6];
    const float* Wo = (const float*)d_in[7];
    const float* bo = (const float*)d_in[8];
    float* out = (float*)d_out;

    proj_qkv<<<dim3(NH, SEQ / 128, 3), 128>>>(x, Wq, bq, Wk, bk, Wv, bv);
    attn_mma<<<dim3(SEQ / 128, NH), 128>>>();
    proj_out<<<dim3(EMB / 64, SEQ / 128), 128>>>(Wo, bo, out);
}

// round 8
// speedup vs baseline: 3.8793x; 1.1703x over previous
#include <cuda_runtime.h>
#include <math.h>
#include <stdint.h>

#define SEQ 4096
#define EMB 768
#define NH  12
#define HD  64

// Scratch (allocation-free rule: __device__ globals).
__device__ float g_qkv[3 * NH * SEQ * HD];   // [which][head][seq][hd]
__device__ float g_attn[NH * SEQ * HD];      // [head][seq][hd]

__device__ __forceinline__ uint32_t f2tf(float f) {
    uint32_t r;
    asm("cvt.rna.tf32.f32 %0, %1;" : "=r"(r) : "f"(f));
    return r;
}
__device__ __forceinline__ float f2tff(float f) { return __uint_as_float(f2tf(f)); }

// pack {hi, lo} floats -> bf16x2
__device__ __forceinline__ uint32_t bf16x2(float hi, float lo) {
    uint32_t d;
    asm("cvt.rn.bf16x2.f32 %0, %1, %2;" : "=r"(d) : "f"(hi), "f"(lo));
    return d;
}

// 16B async copy gmem -> smem
__device__ __forceinline__ void cp16(void* dst_smem, const void* src_gmem) {
    uint32_t s = (uint32_t)__cvta_generic_to_shared(dst_smem);
    asm volatile("cp.async.cg.shared.global [%0], [%1], 16;"
                 :: "r"(s), "l"(src_gmem) : "memory");
}
#define CP_COMMIT() asm volatile("cp.async.commit_group;" ::: "memory")

// D += A(16x8,tf32) * B(8x8,tf32), row.col, fp32 acc.
__device__ __forceinline__ void mma_tf32(float* c,
                                         const uint32_t* a,
                                         uint32_t b0, uint32_t b1) {
    asm volatile(
        "mma.sync.aligned.m16n8k8.row.col.f32.tf32.tf32.f32 "
        "{%0,%1,%2,%3}, {%4,%5,%6,%7}, {%8,%9}, {%0,%1,%2,%3};"
        : "+f"(c[0]), "+f"(c[1]), "+f"(c[2]), "+f"(c[3])
        : "r"(a[0]), "r"(a[1]), "r"(a[2]), "r"(a[3]), "r"(b0), "r"(b1));
}

// D += A(16x16,bf16) * B(16x8,bf16), row.col, fp32 acc.
__device__ __forceinline__ void mma_bf16(float* c,
                                         const uint32_t* a,
                                         uint32_t b0, uint32_t b1) {
    asm volatile(
        "mma.sync.aligned.m16n8k16.row.col.f32.bf16.bf16.f32 "
        "{%0,%1,%2,%3}, {%4,%5,%6,%7}, {%8,%9}, {%0,%1,%2,%3};"
        : "+f"(c[0]), "+f"(c[1]), "+f"(c[2]), "+f"(c[3])
        : "r"(a[0]), "r"(a[1]), "r"(a[2]), "r"(a[3]), "r"(b0), "r"(b1));
}

// ---------------------------------------------------------------------------
// Kernel 1: QKV projections. R8: register-prefetch pipeline — next K-step's
// X/W float4s are loaded during the mma phase and stored (with f2tf) at the
// top of the next iteration. Tile 128x64, K-step 32, warp m32n64.
// ---------------------------------------------------------------------------
__global__ __launch_bounds__(128) void proj_qkv(
    const float* __restrict__ x,
    const float* __restrict__ Wq, const float* __restrict__ bq,
    const float* __restrict__ Wk, const float* __restrict__ bk,
    const float* __restrict__ Wv, const float* __restrict__ bv)
{
    __shared__ float As[128][36];
    __shared__ float Bs[32][72];

    const int which = blockIdx.z;
    const float* W    = (which == 0) ? Wq : (which == 1) ? Wk : Wv;
    const float* bias = (which == 0) ? bq : (which == 1) ? bk : bv;
    const int head = blockIdx.x;
    const int n0 = head * 64;
    const int m0 = blockIdx.y * 128;
    const int tid  = threadIdx.x;
    const int lane = tid & 31, w = tid >> 5;
    const int g = lane >> 2, tig = lane & 3;

    // loader coordinates
    const int xr = tid >> 3, xc = (tid & 7) * 4;      // X: row, col-group base
    const int wr = tid >> 4, wc = (tid & 15) * 4;     // W: row, col

    float acc[2][8][4] = {};
    float4 xv[8], wv[4];

    // prologue: fetch k0 = 0
    #pragma unroll
    for (int rep = 0; rep < 8; rep++)
        xv[rep] = *(const float4*)&x[(size_t)(m0 + rep * 16 + xr) * EMB + xc];
    #pragma unroll
    for (int rep = 0; rep < 4; rep++)
        wv[rep] = *(const float4*)&W[(size_t)(rep * 8 + wr) * EMB + n0 + wc];

    for (int k0 = 0; k0 < EMB; k0 += 32) {
        __syncthreads();                               // prev mma done
        #pragma unroll
        for (int rep = 0; rep < 8; rep++)
            *(float4*)&As[rep * 16 + xr][xc] = make_float4(
                f2tff(xv[rep].x), f2tff(xv[rep].y), f2tff(xv[rep].z), f2tff(xv[rep].w));
        #pragma unroll
        for (int rep = 0; rep < 4; rep++)
            *(float4*)&Bs[rep * 8 + wr][wc] = make_float4(
                f2tff(wv[rep].x), f2tff(wv[rep].y), f2tff(wv[rep].z), f2tff(wv[rep].w));
        if (k0 + 32 < EMB) {                           // prefetch next step
            #pragma unroll
            for (int rep = 0; rep < 8; rep++)
                xv[rep] = *(const float4*)
                    &x[(size_t)(m0 + rep * 16 + xr) * EMB + k0 + 32 + xc];
            #pragma unroll
            for (int rep = 0; rep < 4; rep++)
                wv[rep] = *(const float4*)
                    &W[(size_t)(k0 + 32 + rep * 8 + wr) * EMB + n0 + wc];
        }
        __syncthreads();                               // smem visible
        #pragma unroll
        for (int kh = 0; kh < 4; kh++) {
            uint32_t a[2][4];
            #pragma unroll
            for (int mt = 0; mt < 2; mt++) {
                int mr = w * 32 + mt * 16 + g;
                a[mt][0] = __float_as_uint(As[mr    ][kh * 8 + tig]);
                a[mt][1] = __float_as_uint(As[mr + 8][kh * 8 + tig]);
                a[mt][2] = __float_as_uint(As[mr    ][kh * 8 + tig + 4]);
                a[mt][3] = __float_as_uint(As[mr + 8][kh * 8 + tig + 4]);
            }
            #pragma unroll
            for (int n = 0; n < 8; n++) {
                uint32_t b0 = __float_as_uint(Bs[kh * 8 + tig    ][n * 8 + g]);
                uint32_t b1 = __float_as_uint(Bs[kh * 8 + tig + 4][n * 8 + g]);
                mma_tf32(acc[0][n], a[0], b0, b1);
                mma_tf32(acc[1][n], a[1], b0, b1);
            }
        }
    }

    float* outp = g_qkv + ((size_t)which * NH + head) * (size_t)(SEQ * HD);
    #pragma unroll
    for (int mt = 0; mt < 2; mt++) {
        const int r0 = m0 + w * 32 + mt * 16 + g, r1 = r0 + 8;
        #pragma unroll
        for (int n = 0; n < 8; n++) {
            int cc = n * 8 + 2 * tig;
            float b0 = bias[n0 + cc], b1 = bias[n0 + cc + 1];
            *(float2*)&outp[(size_t)r0 * HD + cc] =
                make_float2(acc[mt][n][0] + b0, acc[mt][n][1] + b1);
            *(float2*)&outp[(size_t)r1 * HD + cc] =
                make_float2(acc[mt][n][2] + b0, acc[mt][n][3] + b1);
        }
    }
}

// ---------------------------------------------------------------------------
// Kernel 2: flash attention. R8 pipeline:
//  - K tiles: cp.async, double-buffered Ks[2], issued one tile ahead
//    (wait_group 1). K fed to mma UNCONVERTED (tf32 truncation => uniform
//    ~5e-4 score shrink, softmax-invariant).
//  - V tiles: LDG-prefetched one tile ahead into registers; bf16 transform +
//    Vt store happen between the two barriers of the consuming iteration
//    (single Vt buffer is hazard-free: write window sits between sync1/sync2).
//  - Compute identical to R7 (two 32-key halves, bf16 P*V).
// ---------------------------------------------------------------------------
__global__ __launch_bounds__(128, 2) void attn_mma()
{
    __shared__ float    Ks[2][64][68];
    __shared__ uint32_t Vt[64][36];    // [hd][key/2]: lo = even key, hi = odd

    const int head = blockIdx.y;
    const int q0 = blockIdx.x * 128;
    const float* Qg = g_qkv + ((size_t)0 * NH + head) * (size_t)(SEQ * HD);
    const float* Kg = g_qkv + ((size_t)1 * NH + head) * (size_t)(SEQ * HD);
    const float* Vg = g_qkv + ((size_t)2 * NH + head) * (size_t)(SEQ * HD);
    const int tid  = threadIdx.x;
    const int lane = tid & 31, w = tid >> 5;
    const int g = lane >> 2, tig = lane & 3;
    const int ldr = tid >> 4, ldc = (tid & 15) * 4;   // loader row/col within tile

    // Q fragments for both m16-subtiles, 1/8 scale folded in (rounded tf32).
    uint32_t qa[2][8][4];
    #pragma unroll
    for (int mt = 0; mt < 2; mt++) {
        const float* qr0 = Qg + (size_t)(q0 + w * 32 + mt * 16 + g) * HD;
        const float* qr1 = qr0 + 8 * HD;
        #pragma unroll
        for (int kc = 0; kc < 8; kc++) {
            qa[mt][kc][0] = f2tf(qr0[kc * 8 + tig]     * 0.125f);
            qa[mt][kc][1] = f2tf(qr1[kc * 8 + tig]     * 0.125f);
            qa[mt][kc][2] = f2tf(qr0[kc * 8 + tig + 4] * 0.125f);
            qa[mt][kc][3] = f2tf(qr1[kc * 8 + tig + 4] * 0.125f);
        }
    }

    float o[2][8][4] = {};
    float mi[2][2], li[2][2];
    #pragma unroll
    for (int mt = 0; mt < 2; mt++) {
        mi[mt][0] = -INFINITY; mi[mt][1] = -INFINITY;
        li[mt][0] = 0.f;       li[mt][1] = 0.f;
    }

    // prologue: tile 0 -> Ks[0] (async) + V tile 0 -> regs
    float4 vreg[8];
    #pragma unroll
    for (int rep = 0; rep < 8; rep++) {
        int r = rep * 8 + ldr;
        cp16(&Ks[0][r][ldc], &Kg[(size_t)r * HD + ldc]);
        vreg[rep] = *(const float4*)&Vg[(size_t)r * HD + ldc];
    }
    CP_COMMIT();

    const int NT = SEQ / 64;
    for (int t = 0; t < NT; ++t) {
        const int cb = t & 1, nb = cb ^ 1;
        const int base1 = (t + 1) * 64;
        __syncthreads();                     // sync1: prev compute fully done

        if (t + 1 < NT) {                    // K tile t+1 -> Ks[nb] (async)
            #pragma unroll
            for (int rep = 0; rep < 8; rep++) {
                int r = rep * 8 + ldr;
                cp16(&Ks[nb][r][ldc], &Kg[(size_t)(base1 + r) * HD + ldc]);
            }
        }
        CP_COMMIT();

        // transform V tile t (in regs) -> Vt
        #pragma unroll
        for (int rep = 0; rep < 8; rep++) {
            int r = rep * 8 + ldr;
            float4 vv = vreg[rep];
            uint32_t p0 = bf16x2(vv.y, vv.x);    // hd ldc+1 | ldc
            uint32_t p1 = bf16x2(vv.w, vv.z);    // hd ldc+3 | ldc+2
            uint32_t s0 = __shfl_xor_sync(0xffffffffu, p0, 16);
            uint32_t s1 = __shfl_xor_sync(0xffffffffu, p1, 16);
            int kw = r >> 1;
            if (lane < 16) {                     // my key even, partner odd
                Vt[ldc + 0][kw] = __byte_perm(p0, s0, 0x5410);
                Vt[ldc + 1][kw] = __byte_perm(p0, s0, 0x7632);
            } else {                             // my key odd, partner even
                Vt[ldc + 2][kw] = __byte_perm(s1, p1, 0x5410);
                Vt[ldc + 3][kw] = __byte_perm(s1, p1, 0x7632);
            }
        }
        if (t + 1 < NT) {                    // prefetch V tile t+1 -> regs
            #pragma unroll
            for (int rep = 0; rep < 8; rep++) {
                int r = rep * 8 + ldr;
                vreg[rep] = *(const float4*)&Vg[(size_t)(base1 + r) * HD + ldc];
            }
            asm volatile("cp.async.wait_group 1;" ::: "memory");
        } else {
            asm volatile("cp.async.wait_group 0;" ::: "memory");
        }
        __syncthreads();                     // sync2: Ks[cb] + Vt visible

        #pragma unroll
        for (int h = 0; h < 2; h++) {        // two 32-key halves
            float s[2][4][4] = {};
            #pragma unroll
            for (int kc = 0; kc < 8; kc++) {
                #pragma unroll
                for (int n = 0; n < 4; n++) {
                    int kr = h * 32 + n * 8 + g;
                    uint32_t b0 = __float_as_uint(Ks[cb][kr][kc * 8 + tig]);
                    uint32_t b1 = __float_as_uint(Ks[cb][kr][kc * 8 + tig + 4]);
                    mma_tf32(s[0][n], qa[0][kc], b0, b1);
                    mma_tf32(s[1][n], qa[1][kc], b0, b1);
                }
            }

            #pragma unroll
            for (int mt = 0; mt < 2; mt++) {
                float mx0 = -INFINITY, mx1 = -INFINITY;
                #pragma unroll
                for (int n = 0; n < 4; n++) {
                    mx0 = fmaxf(mx0, fmaxf(s[mt][n][0], s[mt][n][1]));
                    mx1 = fmaxf(mx1, fmaxf(s[mt][n][2], s[mt][n][3]));
                }
                mx0 = fmaxf(mx0, __shfl_xor_sync(0xffffffffu, mx0, 1));
                mx0 = fmaxf(mx0, __shfl_xor_sync(0xffffffffu, mx0, 2));
                mx1 = fmaxf(mx1, __shfl_xor_sync(0xffffffffu, mx1, 1));
                mx1 = fmaxf(mx1, __shfl_xor_sync(0xffffffffu, mx1, 2));
                float nm0 = fmaxf(mi[mt][0], mx0), nm1 = fmaxf(mi[mt][1], mx1);
                float sc0 = __expf(mi[mt][0] - nm0), sc1 = __expf(mi[mt][1] - nm1);
                mi[mt][0] = nm0; mi[mt][1] = nm1;
                float sum0 = 0.f, sum1 = 0.f;
                #pragma unroll
                for (int n = 0; n < 4; n++) {
                    s[mt][n][0] = __expf(s[mt][n][0] - nm0); sum0 += s[mt][n][0];
                    s[mt][n][1] = __expf(s[mt][n][1] - nm0); sum0 += s[mt][n][1];
                    s[mt][n][2] = __expf(s[mt][n][2] - nm1); sum1 += s[mt][n][2];
                    s[mt][n][3] = __expf(s[mt][n][3] - nm1); sum1 += s[mt][n][3];
                }
                sum0 += __shfl_xor_sync(0xffffffffu, sum0, 1);
                sum0 += __shfl_xor_sync(0xffffffffu, sum0, 2);
                sum1 += __shfl_xor_sync(0xffffffffu, sum1, 1);
                sum1 += __shfl_xor_sync(0xffffffffu, sum1, 2);
                li[mt][0] = li[mt][0] * sc0 + sum0;
                li[mt][1] = li[mt][1] * sc1 + sum1;
                #pragma unroll
                for (int n = 0; n < 8; n++) {
                    o[mt][n][0] *= sc0; o[mt][n][1] *= sc0;
                    o[mt][n][2] *= sc1; o[mt][n][3] *= sc1;
                }
            }

            uint32_t pk[2][2][4];
            #pragma unroll
            for (int mt = 0; mt < 2; mt++)
                #pragma unroll
                for (int kc2 = 0; kc2 < 2; kc2++) {
                    pk[mt][kc2][0] = bf16x2(s[mt][2*kc2  ][1], s[mt][2*kc2  ][0]);
                    pk[mt][kc2][1] = bf16x2(s[mt][2*kc2  ][3], s[mt][2*kc2  ][2]);
                    pk[mt][kc2][2] = bf16x2(s[mt][2*kc2+1][1], s[mt][2*kc2+1][0]);
                    pk[mt][kc2][3] = bf16x2(s[mt][2*kc2+1][3], s[mt][2*kc2+1][2]);
                }

            #pragma unroll
            for (int kc2 = 0; kc2 < 2; kc2++) {
                #pragma unroll
                for (int n = 0; n < 8; n++) {
                    uint32_t b0 = Vt[n * 8 + g][h * 16 + kc2 * 8 + tig];
                    uint32_t b1 = Vt[n * 8 + g][h * 16 + kc2 * 8 + tig + 4];
                    mma_bf16(o[0][n], pk[0][kc2], b0, b1);
                    mma_bf16(o[1][n], pk[1][kc2], b0, b1);
                }
            }
        }
    }

    float* Og = g_attn + (size_t)head * (size_t)(SEQ * HD);
    #pragma unroll
    for (int mt = 0; mt < 2; mt++) {
        float inv0 = 1.0f / li[mt][0], inv1 = 1.0f / li[mt][1];
        const int r0 = q0 + w * 32 + mt * 16 + g, r1 = r0 + 8;
        #pragma unroll
        for (int n = 0; n < 8; n++) {
            int cc = n * 8 + 2 * tig;
            *(float2*)&Og[(size_t)r0 * HD + cc] =
                make_float2(o[mt][n][0] * inv0, o[mt][n][1] * inv0);
            *(float2*)&Og[(size_t)r1 * HD + cc] =
                make_float2(o[mt][n][2] * inv1, o[mt][n][3] * inv1);
        }
    }
}

// ---------------------------------------------------------------------------
// Kernel 3: output projection, register-prefetch pipeline (A gathers heads).
// ---------------------------------------------------------------------------
__global__ __launch_bounds__(128) void proj_out(
    const float* __restrict__ Wo, const float* __restrict__ bo,
    float* __restrict__ out)
{
    __shared__ float As[128][36];
    __shared__ float Bs[32][72];

    const int n0 = blockIdx.x * 64;
    const int m0 = blockIdx.y * 128;
    const int tid  = threadIdx.x;
    const int lane = tid & 31, w = tid >> 5;
    const int g = lane >> 2, tig = lane & 3;
    const int xr = tid >> 3, xc = (tid & 7) * 4;
    const int wr = tid >> 4, wc = (tid & 15) * 4;

    float acc[2][8][4] = {};
    float4 xv[8], wv[4];

    // prologue k0 = 0 (head 0, d0 = 0)
    #pragma unroll
    for (int rep = 0; rep < 8; rep++)
        xv[rep] = *(const float4*)&g_attn[((size_t)0 * SEQ + m0 + rep * 16 + xr) * HD + xc];
    #pragma unroll
    for (int rep = 0; rep < 4; rep++)
        wv[rep] = *(const float4*)&Wo[(size_t)(rep * 8 + wr) * EMB + n0 + wc];

    for (int k0 = 0; k0 < EMB; k0 += 32) {
        __syncthreads();
        #pragma unroll
        for (int rep = 0; rep < 8; rep++)
            *(float4*)&As[rep * 16 + xr][xc] = make_float4(
                f2tff(xv[rep].x), f2tff(xv[rep].y), f2tff(xv[rep].z), f2tff(xv[rep].w));
        #pragma unroll
        for (int rep = 0; rep < 4; rep++)
            *(float4*)&Bs[rep * 8 + wr][wc] = make_float4(
                f2tff(wv[rep].x), f2tff(wv[rep].y), f2tff(wv[rep].z), f2tff(wv[rep].w));
        if (k0 + 32 < EMB) {
            int k = k0 + 32;
            int h = k >> 6, d0 = k & 63;
            #pragma unroll
            for (int rep = 0; rep < 8; rep++)
                xv[rep] = *(const float4*)
                    &g_attn[((size_t)h * SEQ + m0 + rep * 16 + xr) * HD + d0 + xc];
            #pragma unroll
            for (int rep = 0; rep < 4; rep++)
                wv[rep] = *(const float4*)
                    &Wo[(size_t)(k + rep * 8 + wr) * EMB + n0 + wc];
        }
        __syncthreads();
        #pragma unroll
        for (int kh = 0; kh < 4; kh++) {
            uint32_t a[2][4];
            #pragma unroll
            for (int mt = 0; mt < 2; mt++) {
                int mr = w * 32 + mt * 16 + g;
                a[mt][0] = __float_as_uint(As[mr    ][kh * 8 + tig]);
                a[mt][1] = __float_as_uint(As[mr + 8][kh * 8 + tig]);
                a[mt][2] = __float_as_uint(As[mr    ][kh * 8 + tig + 4]);
                a[mt][3] = __float_as_uint(As[mr + 8][kh * 8 + tig + 4]);
            }
            #pragma unroll
            for (int n = 0; n < 8; n++) {
                uint32_t b0 = __float_as_uint(Bs[kh * 8 + tig    ][n * 8 + g]);
                uint32_t b1 = __float_as_uint(Bs[kh * 8 + tig + 4][n * 8 + g]);
                mma_tf32(acc[0][n], a[0], b0, b1);
                mma_tf32(acc[1][n], a[1], b0, b1);
            }
        }
    }

    #pragma unroll
    for (int mt = 0; mt < 2; mt++) {
        const int r0 = m0 + w * 32 + mt * 16 + g, r1 = r0 + 8;
        #pragma unroll
        for (int n = 0; n < 8; n++) {
            int cc = n0 + n * 8 + 2 * tig;
            float b0 = bo[cc], b1 = bo[cc + 1];
            *(float2*)&out[(size_t)r0 * EMB + cc] =
                make_float2(acc[mt][n][0] + b0, acc[mt][n][1] + b1);
            *(float2*)&out[(size_t)r1 * EMB + cc] =
                make_float2(acc[mt][n][2] + b0, acc[mt][n][3] + b1);
        }
    }
}

// ---------------------------------------------------------------------------
// Launch. Input order (metadata): x, Wk, bk, Wq, bq, Wv, bv, Wo, bo.
// ---------------------------------------------------------------------------
extern "C" void kernel_launch(void* const* d_in, const int* in_sizes, int n_in,
                              void* d_out, int out_size)
{
    const float* x  = (const float*)d_in[0];
    const float* Wk = (const float*)d_in[1];
    const float* bk = (const float*)d_in[2];
    const float* Wq = (const float*)d_in[3];
    const float* bq = (const float*)d_in[4];
    const float* Wv = (const float*)d_in[5];
    const float* bv = (const float*)d_in[6];
    const float* Wo = (const float*)d_in[7];
    const float* bo = (const float*)d_in[8];
    float* out = (float*)d_out;

    proj_qkv<<<dim3(NH, SEQ / 128, 3), 128>>>(x, Wq, bq, Wk, bk, Wv, bv);
    attn_mma<<<dim3(SEQ / 128, NH), 128>>>();
    proj_out<<<dim3(EMB / 64, SEQ / 128), 128>>>(Wo, bo, out);
}

// round 9
// speedup vs baseline: 6.2285x; 1.6056x over previous
#include <cuda_runtime.h>
#include <math.h>
#include <stdint.h>

#define SEQ 4096
#define EMB 768
#define NH  12
#define HD  64

// Scratch (allocation-free rule: __device__ globals).
__device__ __align__(16) float    g_q[NH * SEQ * HD];          // fp32 Q [head][seq][hd]
__device__ __align__(16) uint32_t g_kb[NH * SEQ * (HD / 2)];   // bf16x2 K [head][key][32w] (d pairs)
__device__ __align__(16) uint32_t g_vb[NH * HD * (SEQ / 2)];   // bf16x2 V^T [head][d][key/2]
__device__ __align__(16) float    g_attn[NH * SEQ * HD];       // fp32 attn out [head][seq][hd]

__device__ __forceinline__ uint32_t f2tf(float f) {
    uint32_t r;
    asm("cvt.rna.tf32.f32 %0, %1;" : "=r"(r) : "f"(f));
    return r;
}
__device__ __forceinline__ float f2tff(float f) { return __uint_as_float(f2tf(f)); }

// pack {hi, lo} floats -> bf16x2
__device__ __forceinline__ uint32_t bf16x2(float hi, float lo) {
    uint32_t d;
    asm("cvt.rn.bf16x2.f32 %0, %1, %2;" : "=r"(d) : "f"(hi), "f"(lo));
    return d;
}

// 16B async copy gmem -> smem
__device__ __forceinline__ void cp16(void* dst_smem, const void* src_gmem) {
    uint32_t s = (uint32_t)__cvta_generic_to_shared(dst_smem);
    asm volatile("cp.async.cg.shared.global [%0], [%1], 16;"
                 :: "r"(s), "l"(src_gmem) : "memory");
}
#define CP_COMMIT() asm volatile("cp.async.commit_group;" ::: "memory")

// D += A(16x8,tf32) * B(8x8,tf32), row.col, fp32 acc.
__device__ __forceinline__ void mma_tf32(float* c,
                                         const uint32_t* a,
                                         uint32_t b0, uint32_t b1) {
    asm volatile(
        "mma.sync.aligned.m16n8k8.row.col.f32.tf32.tf32.f32 "
        "{%0,%1,%2,%3}, {%4,%5,%6,%7}, {%8,%9}, {%0,%1,%2,%3};"
        : "+f"(c[0]), "+f"(c[1]), "+f"(c[2]), "+f"(c[3])
        : "r"(a[0]), "r"(a[1]), "r"(a[2]), "r"(a[3]), "r"(b0), "r"(b1));
}

// D += A(16x16,bf16) * B(16x8,bf16), row.col, fp32 acc.
__device__ __forceinline__ void mma_bf16(float* c,
                                         const uint32_t* a,
                                         uint32_t b0, uint32_t b1) {
    asm volatile(
        "mma.sync.aligned.m16n8k16.row.col.f32.bf16.bf16.f32 "
        "{%0,%1,%2,%3}, {%4,%5,%6,%7}, {%8,%9}, {%0,%1,%2,%3};"
        : "+f"(c[0]), "+f"(c[1]), "+f"(c[2]), "+f"(c[3])
        : "r"(a[0]), "r"(a[1]), "r"(a[2]), "r"(a[3]), "r"(b0), "r"(b1));
}

// ---------------------------------------------------------------------------
// Kernel 1: QKV projections (tf32 mma, register-prefetch pipeline, as R8).
// R9: per-`which` epilogues — Q fp32; K packed bf16 row-major (g_kb);
// V packed bf16 TRANSPOSED (g_vb) via shfl pair-exchange.
// ---------------------------------------------------------------------------
__global__ __launch_bounds__(128) void proj_qkv(
    const float* __restrict__ x,
    const float* __restrict__ Wq, const float* __restrict__ bq,
    const float* __restrict__ Wk, const float* __restrict__ bk,
    const float* __restrict__ Wv, const float* __restrict__ bv)
{
    __shared__ float As[128][36];
    __shared__ float Bs[32][72];

    const int which = blockIdx.z;
    const float* W    = (which == 0) ? Wq : (which == 1) ? Wk : Wv;
    const float* bias = (which == 0) ? bq : (which == 1) ? bk : bv;
    const int head = blockIdx.x;
    const int n0 = head * 64;
    const int m0 = blockIdx.y * 128;
    const int tid  = threadIdx.x;
    const int lane = tid & 31, w = tid >> 5;
    const int g = lane >> 2, tig = lane & 3;

    const int xr = tid >> 3, xc = (tid & 7) * 4;
    const int wr = tid >> 4, wc = (tid & 15) * 4;

    float acc[2][8][4] = {};
    float4 xv[8], wv[4];

    #pragma unroll
    for (int rep = 0; rep < 8; rep++)
        xv[rep] = *(const float4*)&x[(size_t)(m0 + rep * 16 + xr) * EMB + xc];
    #pragma unroll
    for (int rep = 0; rep < 4; rep++)
        wv[rep] = *(const float4*)&W[(size_t)(rep * 8 + wr) * EMB + n0 + wc];

    for (int k0 = 0; k0 < EMB; k0 += 32) {
        __syncthreads();
        #pragma unroll
        for (int rep = 0; rep < 8; rep++)
            *(float4*)&As[rep * 16 + xr][xc] = make_float4(
                f2tff(xv[rep].x), f2tff(xv[rep].y), f2tff(xv[rep].z), f2tff(xv[rep].w));
        #pragma unroll
        for (int rep = 0; rep < 4; rep++)
            *(float4*)&Bs[rep * 8 + wr][wc] = make_float4(
                f2tff(wv[rep].x), f2tff(wv[rep].y), f2tff(wv[rep].z), f2tff(wv[rep].w));
        if (k0 + 32 < EMB) {
            #pragma unroll
            for (int rep = 0; rep < 8; rep++)
                xv[rep] = *(const float4*)
                    &x[(size_t)(m0 + rep * 16 + xr) * EMB + k0 + 32 + xc];
            #pragma unroll
            for (int rep = 0; rep < 4; rep++)
                wv[rep] = *(const float4*)
                    &W[(size_t)(k0 + 32 + rep * 8 + wr) * EMB + n0 + wc];
        }
        __syncthreads();
        #pragma unroll
        for (int kh = 0; kh < 4; kh++) {
            uint32_t a[2][4];
            #pragma unroll
            for (int mt = 0; mt < 2; mt++) {
                int mr = w * 32 + mt * 16 + g;
                a[mt][0] = __float_as_uint(As[mr    ][kh * 8 + tig]);
                a[mt][1] = __float_as_uint(As[mr + 8][kh * 8 + tig]);
                a[mt][2] = __float_as_uint(As[mr    ][kh * 8 + tig + 4]);
                a[mt][3] = __float_as_uint(As[mr + 8][kh * 8 + tig + 4]);
            }
            #pragma unroll
            for (int n = 0; n < 8; n++) {
                uint32_t b0 = __float_as_uint(Bs[kh * 8 + tig    ][n * 8 + g]);
                uint32_t b1 = __float_as_uint(Bs[kh * 8 + tig + 4][n * 8 + g]);
                mma_tf32(acc[0][n], a[0], b0, b1);
                mma_tf32(acc[1][n], a[1], b0, b1);
            }
        }
    }

    if (which == 0) {               // Q: fp32, row-major
        float* outp = g_q + (size_t)head * (SEQ * HD);
        #pragma unroll
        for (int mt = 0; mt < 2; mt++) {
            const int r0 = m0 + w * 32 + mt * 16 + g, r1 = r0 + 8;
            #pragma unroll
            for (int n = 0; n < 8; n++) {
                int cc = n * 8 + 2 * tig;
                float b0 = bias[n0 + cc], b1 = bias[n0 + cc + 1];
                *(float2*)&outp[(size_t)r0 * HD + cc] =
                    make_float2(acc[mt][n][0] + b0, acc[mt][n][1] + b1);
                *(float2*)&outp[(size_t)r1 * HD + cc] =
                    make_float2(acc[mt][n][2] + b0, acc[mt][n][3] + b1);
            }
        }
    } else if (which == 1) {        // K: bf16x2 words, row-major (d pairs)
        uint32_t* outp = g_kb + (size_t)head * (SEQ * HD / 2);
        #pragma unroll
        for (int mt = 0; mt < 2; mt++) {
            const int r0 = m0 + w * 32 + mt * 16 + g, r1 = r0 + 8;
            #pragma unroll
            for (int n = 0; n < 8; n++) {
                int cc = n * 8 + 2 * tig;
                float b0 = bias[n0 + cc], b1 = bias[n0 + cc + 1];
                outp[(size_t)r0 * 32 + n * 4 + tig] =
                    bf16x2(acc[mt][n][1] + b1, acc[mt][n][0] + b0);
                outp[(size_t)r1 * 32 + n * 4 + tig] =
                    bf16x2(acc[mt][n][3] + b1, acc[mt][n][2] + b0);
            }
        }
    } else {                        // V: bf16x2 words, transposed [d][key/2]
        uint32_t* outp = g_vb + (size_t)head * (HD * SEQ / 2);
        const bool evn = (lane & 4) == 0;      // g even -> even key rows
        #pragma unroll
        for (int mt = 0; mt < 2; mt++) {
            const int r0 = m0 + w * 32 + mt * 16 + g, r1 = r0 + 8;
            const int kw0 = r0 >> 1, kw1 = r1 >> 1;   // same for partner lane
            #pragma unroll
            for (int n = 0; n < 8; n++) {
                int cc = n * 8 + 2 * tig;
                float b0 = bias[n0 + cc], b1 = bias[n0 + cc + 1];
                uint32_t p0 = bf16x2(acc[mt][n][1] + b1, acc[mt][n][0] + b0); // r0: hi=cc+1, lo=cc
                uint32_t p1 = bf16x2(acc[mt][n][3] + b1, acc[mt][n][2] + b0); // r1
                uint32_t q0 = __shfl_xor_sync(0xffffffffu, p0, 4);
                uint32_t q1 = __shfl_xor_sync(0xffffffffu, p1, 4);
                if (evn) {   // write d = cc words (lo = my even key, hi = partner odd)
                    outp[(size_t)cc * (SEQ / 2) + kw0] = __byte_perm(p0, q0, 0x5410);
                    outp[(size_t)cc * (SEQ / 2) + kw1] = __byte_perm(p1, q1, 0x5410);
                } else {     // write d = cc+1 words (lo = partner even, hi = my odd)
                    outp[(size_t)(cc + 1) * (SEQ / 2) + kw0] = __byte_perm(p0, q0, 0x3276);
                    outp[(size_t)(cc + 1) * (SEQ / 2) + kw1] = __byte_perm(p1, q1, 0x3276);
                }
            }
        }
    }
}

// ---------------------------------------------------------------------------
// Kernel 2: flash attention, all-bf16 mma. Block 128 thr, 128 q-rows.
// K and V tiles arrive via cp.async ALREADY in mma-B layout (double-buffered).
// QK^T: m16n8k16 bf16 (4 k-steps); P·V: m16n8k16 bf16. No in-kernel
// convert/transpose. Smem rows padded to 36 words -> all B-frag reads
// bank-conflict-free (bank = 4g + 8kc + tig).
// ---------------------------------------------------------------------------
__global__ __launch_bounds__(128, 2) void attn_mma()
{
    __shared__ __align__(16) uint32_t Kb[2][64][36];   // [key][d/2]
    __shared__ __align__(16) uint32_t Vt[2][64][36];   // [d][key/2]

    const int head = blockIdx.y;
    const int q0 = blockIdx.x * 128;
    const float*    Qg = g_q  + (size_t)head * (SEQ * HD);
    const uint32_t* Kg = g_kb + (size_t)head * (SEQ * HD / 2);
    const uint32_t* Vg = g_vb + (size_t)head * (HD * SEQ / 2);
    const int tid  = threadIdx.x;
    const int lane = tid & 31, w = tid >> 5;
    const int g = lane >> 2, tig = lane & 3;
    const int lr = tid >> 3, lc4 = (tid & 7) * 4;      // loader: row, word-chunk base

    // Q -> bf16 A-frags (k16), 1/8 scale folded. qa[mt][kc][0..3]
    uint32_t qa[2][4][4];
    #pragma unroll
    for (int mt = 0; mt < 2; mt++) {
        const float* qr0 = Qg + (size_t)(q0 + w * 32 + mt * 16 + g) * HD;
        const float* qr1 = qr0 + 8 * HD;
        #pragma unroll
        for (int kc = 0; kc < 4; kc++) {
            int d = kc * 16 + 2 * tig;
            qa[mt][kc][0] = bf16x2(qr0[d + 1] * 0.125f, qr0[d] * 0.125f);
            qa[mt][kc][1] = bf16x2(qr1[d + 1] * 0.125f, qr1[d] * 0.125f);
            qa[mt][kc][2] = bf16x2(qr0[d + 9] * 0.125f, qr0[d + 8] * 0.125f);
            qa[mt][kc][3] = bf16x2(qr1[d + 9] * 0.125f, qr1[d + 8] * 0.125f);
        }
    }

    float o[2][8][4] = {};
    float mi[2][2], li[2][2];
    #pragma unroll
    for (int mt = 0; mt < 2; mt++) {
        mi[mt][0] = -INFINITY; mi[mt][1] = -INFINITY;
        li[mt][0] = 0.f;       li[mt][1] = 0.f;
    }

    // prologue: tile 0 -> buf 0 (K rows: 32 words each; V rows: 32-word slices)
    #pragma unroll
    for (int rep = 0; rep < 4; rep++) {
        int r = rep * 16 + lr;
        cp16(&Kb[0][r][lc4], &Kg[(size_t)r * 32 + lc4]);
        cp16(&Vt[0][r][lc4], &Vg[(size_t)r * (SEQ / 2) + lc4]);
    }
    CP_COMMIT();

    const int NT = SEQ / 64;
    for (int t = 0; t < NT; ++t) {
        const int cb = t & 1, nb = cb ^ 1;
        __syncthreads();                     // sync1: all compute on nb done

        if (t + 1 < NT) {
            const int kbase = (t + 1) * 64, wbase = (t + 1) * 32;
            #pragma unroll
            for (int rep = 0; rep < 4; rep++) {
                int r = rep * 16 + lr;
                cp16(&Kb[nb][r][lc4], &Kg[(size_t)(kbase + r) * 32 + lc4]);
                cp16(&Vt[nb][r][lc4], &Vg[(size_t)r * (SEQ / 2) + wbase + lc4]);
            }
            CP_COMMIT();
            asm volatile("cp.async.wait_group 1;" ::: "memory");
        } else {
            asm volatile("cp.async.wait_group 0;" ::: "memory");
        }
        __syncthreads();                     // sync2: buf cb visible

        #pragma unroll
        for (int h = 0; h < 2; h++) {        // two 32-key halves
            // S = Q K^T (bf16 k16; b-frags shared across mt)
            float s[2][4][4] = {};
            #pragma unroll
            for (int kc = 0; kc < 4; kc++) {
                #pragma unroll
                for (int n = 0; n < 4; n++) {
                    int kr = h * 32 + n * 8 + g;
                    uint32_t b0 = Kb[cb][kr][kc * 8 + tig];
                    uint32_t b1 = Kb[cb][kr][kc * 8 + tig + 4];
                    mma_bf16(s[0][n], qa[0][kc], b0, b1);
                    mma_bf16(s[1][n], qa[1][kc], b0, b1);
                }
            }

            // online softmax (rows g / g+8 per subtile)
            #pragma unroll
            for (int mt = 0; mt < 2; mt++) {
                float mx0 = -INFINITY, mx1 = -INFINITY;
                #pragma unroll
                for (int n = 0; n < 4; n++) {
                    mx0 = fmaxf(mx0, fmaxf(s[mt][n][0], s[mt][n][1]));
                    mx1 = fmaxf(mx1, fmaxf(s[mt][n][2], s[mt][n][3]));
                }
                mx0 = fmaxf(mx0, __shfl_xor_sync(0xffffffffu, mx0, 1));
                mx0 = fmaxf(mx0, __shfl_xor_sync(0xffffffffu, mx0, 2));
                mx1 = fmaxf(mx1, __shfl_xor_sync(0xffffffffu, mx1, 1));
                mx1 = fmaxf(mx1, __shfl_xor_sync(0xffffffffu, mx1, 2));
                float nm0 = fmaxf(mi[mt][0], mx0), nm1 = fmaxf(mi[mt][1], mx1);
                float sc0 = __expf(mi[mt][0] - nm0), sc1 = __expf(mi[mt][1] - nm1);
                mi[mt][0] = nm0; mi[mt][1] = nm1;
                float sum0 = 0.f, sum1 = 0.f;
                #pragma unroll
                for (int n = 0; n < 4; n++) {
                    s[mt][n][0] = __expf(s[mt][n][0] - nm0); sum0 += s[mt][n][0];
                    s[mt][n][1] = __expf(s[mt][n][1] - nm0); sum0 += s[mt][n][1];
                    s[mt][n][2] = __expf(s[mt][n][2] - nm1); sum1 += s[mt][n][2];
                    s[mt][n][3] = __expf(s[mt][n][3] - nm1); sum1 += s[mt][n][3];
                }
                sum0 += __shfl_xor_sync(0xffffffffu, sum0, 1);
                sum0 += __shfl_xor_sync(0xffffffffu, sum0, 2);
                sum1 += __shfl_xor_sync(0xffffffffu, sum1, 1);
                sum1 += __shfl_xor_sync(0xffffffffu, sum1, 2);
                li[mt][0] = li[mt][0] * sc0 + sum0;
                li[mt][1] = li[mt][1] * sc1 + sum1;
                #pragma unroll
                for (int n = 0; n < 8; n++) {
                    o[mt][n][0] *= sc0; o[mt][n][1] *= sc0;
                    o[mt][n][2] *= sc1; o[mt][n][3] *= sc1;
                }
            }

            // P: C-frags -> bf16 A-frags (registers only)
            uint32_t pk[2][2][4];
            #pragma unroll
            for (int mt = 0; mt < 2; mt++)
                #pragma unroll
                for (int kc2 = 0; kc2 < 2; kc2++) {
                    pk[mt][kc2][0] = bf16x2(s[mt][2*kc2  ][1], s[mt][2*kc2  ][0]);
                    pk[mt][kc2][1] = bf16x2(s[mt][2*kc2  ][3], s[mt][2*kc2  ][2]);
                    pk[mt][kc2][2] = bf16x2(s[mt][2*kc2+1][1], s[mt][2*kc2+1][0]);
                    pk[mt][kc2][3] = bf16x2(s[mt][2*kc2+1][3], s[mt][2*kc2+1][2]);
                }

            // O += P V
            #pragma unroll
            for (int kc2 = 0; kc2 < 2; kc2++) {
                #pragma unroll
                for (int n = 0; n < 8; n++) {
                    uint32_t b0 = Vt[cb][n * 8 + g][h * 16 + kc2 * 8 + tig];
                    uint32_t b1 = Vt[cb][n * 8 + g][h * 16 + kc2 * 8 + tig + 4];
                    mma_bf16(o[0][n], pk[0][kc2], b0, b1);
                    mma_bf16(o[1][n], pk[1][kc2], b0, b1);
                }
            }
        }
    }

    float* Og = g_attn + (size_t)head * (SEQ * HD);
    #pragma unroll
    for (int mt = 0; mt < 2; mt++) {
        float inv0 = 1.0f / li[mt][0], inv1 = 1.0f / li[mt][1];
        const int r0 = q0 + w * 32 + mt * 16 + g, r1 = r0 + 8;
        #pragma unroll
        for (int n = 0; n < 8; n++) {
            int cc = n * 8 + 2 * tig;
            *(float2*)&Og[(size_t)r0 * HD + cc] =
                make_float2(o[mt][n][0] * inv0, o[mt][n][1] * inv0);
            *(float2*)&Og[(size_t)r1 * HD + cc] =
                make_float2(o[mt][n][2] * inv1, o[mt][n][3] * inv1);
        }
    }
}

// ---------------------------------------------------------------------------
// Kernel 3: output projection (unchanged from R8).
// ---------------------------------------------------------------------------
__global__ __launch_bounds__(128) void proj_out(
    const float* __restrict__ Wo, const float* __restrict__ bo,
    float* __restrict__ out)
{
    __shared__ float As[128][36];
    __shared__ float Bs[32][72];

    const int n0 = blockIdx.x * 64;
    const int m0 = blockIdx.y * 128;
    const int tid  = threadIdx.x;
    const int lane = tid & 31, w = tid >> 5;
    const int g = lane >> 2, tig = lane & 3;
    const int xr = tid >> 3, xc = (tid & 7) * 4;
    const int wr = tid >> 4, wc = (tid & 15) * 4;

    float acc[2][8][4] = {};
    float4 xv[8], wv[4];

    #pragma unroll
    for (int rep = 0; rep < 8; rep++)
        xv[rep] = *(const float4*)&g_attn[((size_t)0 * SEQ + m0 + rep * 16 + xr) * HD + xc];
    #pragma unroll
    for (int rep = 0; rep < 4; rep++)
        wv[rep] = *(const float4*)&Wo[(size_t)(rep * 8 + wr) * EMB + n0 + wc];

    for (int k0 = 0; k0 < EMB; k0 += 32) {
        __syncthreads();
        #pragma unroll
        for (int rep = 0; rep < 8; rep++)
            *(float4*)&As[rep * 16 + xr][xc] = make_float4(
                f2tff(xv[rep].x), f2tff(xv[rep].y), f2tff(xv[rep].z), f2tff(xv[rep].w));
        #pragma unroll
        for (int rep = 0; rep < 4; rep++)
            *(float4*)&Bs[rep * 8 + wr][wc] = make_float4(
                f2tff(wv[rep].x), f2tff(wv[rep].y), f2tff(wv[rep].z), f2tff(wv[rep].w));
        if (k0 + 32 < EMB) {
            int k = k0 + 32;
            int h = k >> 6, d0 = k & 63;
            #pragma unroll
            for (int rep = 0; rep < 8; rep++)
                xv[rep] = *(const float4*)
                    &g_attn[((size_t)h * SEQ + m0 + rep * 16 + xr) * HD + d0 + xc];
            #pragma unroll
            for (int rep = 0; rep < 4; rep++)
                wv[rep] = *(const float4*)
                    &Wo[(size_t)(k + rep * 8 + wr) * EMB + n0 + wc];
        }
        __syncthreads();
        #pragma unroll
        for (int kh = 0; kh < 4; kh++) {
            uint32_t a[2][4];
            #pragma unroll
            for (int mt = 0; mt < 2; mt++) {
                int mr = w * 32 + mt * 16 + g;
                a[mt][0] = __float_as_uint(As[mr    ][kh * 8 + tig]);
                a[mt][1] = __float_as_uint(As[mr + 8][kh * 8 + tig]);
                a[mt][2] = __float_as_uint(As[mr    ][kh * 8 + tig + 4]);
                a[mt][3] = __float_as_uint(As[mr + 8][kh * 8 + tig + 4]);
            }
            #pragma unroll
            for (int n = 0; n < 8; n++) {
                uint32_t b0 = __float_as_uint(Bs[kh * 8 + tig    ][n * 8 + g]);
                uint32_t b1 = __float_as_uint(Bs[kh * 8 + tig + 4][n * 8 + g]);
                mma_tf32(acc[0][n], a[0], b0, b1);
                mma_tf32(acc[1][n], a[1], b0, b1);
            }
        }
    }

    #pragma unroll
    for (int mt = 0; mt < 2; mt++) {
        const int r0 = m0 + w * 32 + mt * 16 + g, r1 = r0 + 8;
        #pragma unroll
        for (int n = 0; n < 8; n++) {
            int cc = n0 + n * 8 + 2 * tig;
            float b0 = bo[cc], b1 = bo[cc + 1];
            *(float2*)&out[(size_t)r0 * EMB + cc] =
                make_float2(acc[mt][n][0] + b0, acc[mt][n][1] + b1);
            *(float2*)&out[(size_t)r1 * EMB + cc] =
                make_float2(acc[mt][n][2] + b0, acc[mt][n][3] + b1);
        }
    }
}

// ---------------------------------------------------------------------------
// Launch. Input order (metadata): x, Wk, bk, Wq, bq, Wv, bv, Wo, bo.
// ---------------------------------------------------------------------------
extern "C" void kernel_launch(void* const* d_in, const int* in_sizes, int n_in,
                              void* d_out, int out_size)
{
    const float* x  = (const float*)d_in[0];
    const float* Wk = (const float*)d_in[1];
    const float* bk = (const float*)d_in[2];
    const float* Wq = (const float*)d_in[3];
    const float* bq = (const float*)d_in[4];
    const float* Wv = (const float*)d_in[5];
    const float* bv = (const float*)d_in[6];
    const float* Wo = (const float*)d_in[7];
    const float* bo = (const float*)d_in[8];
    float* out = (float*)d_out;

    proj_qkv<<<dim3(NH, SEQ / 128, 3), 128>>>(x, Wq, bq, Wk, bk, Wv, bv);
    attn_mma<<<dim3(SEQ / 128, NH), 128>>>();
    proj_out<<<dim3(EMB / 64, SEQ / 128), 128>>>(Wo, bo, out);
}

// round 10
// speedup vs baseline: 6.4771x; 1.0399x over previous
#include <cuda_runtime.h>
#include <math.h>
#include <stdint.h>

#define SEQ 4096
#define EMB 768
#define NH  12
#define HD  64
#define WSZ (768 * 768)

// Scratch (allocation-free rule: __device__ globals).
__device__ __align__(16) float    g_xr[SEQ * EMB];             // tf32-rounded x
__device__ __align__(16) float    g_wt[4 * WSZ];               // tf32-rounded W^T [which][out][in]
__device__ __align__(16) float    g_q[NH * SEQ * HD];          // fp32 Q
__device__ __align__(16) uint32_t g_kb[NH * SEQ * (HD / 2)];   // bf16x2 K [head][key][32w]
__device__ __align__(16) uint32_t g_vb[NH * HD * (SEQ / 2)];   // bf16x2 V^T [head][d][key/2]
__device__ __align__(16) float    g_attn[NH * SEQ * HD];       // tf32-rounded attn out

__device__ __forceinline__ uint32_t f2tf(float f) {
    uint32_t r;
    asm("cvt.rna.tf32.f32 %0, %1;" : "=r"(r) : "f"(f));
    return r;
}
__device__ __forceinline__ float f2tff(float f) { return __uint_as_float(f2tf(f)); }

__device__ __forceinline__ uint32_t bf16x2(float hi, float lo) {
    uint32_t d;
    asm("cvt.rn.bf16x2.f32 %0, %1, %2;" : "=r"(d) : "f"(hi), "f"(lo));
    return d;
}

__device__ __forceinline__ void cp16(void* dst_smem, const void* src_gmem) {
    uint32_t s = (uint32_t)__cvta_generic_to_shared(dst_smem);
    asm volatile("cp.async.cg.shared.global [%0], [%1], 16;"
                 :: "r"(s), "l"(src_gmem) : "memory");
}
#define CP_COMMIT() asm volatile("cp.async.commit_group;" ::: "memory")

// 4x m8n8 b16 matrices; lane l receives (row l>>2, 4B-word l&3) of matrix j in r_j.
__device__ __forceinline__ void ldm_x4(uint32_t& r0, uint32_t& r1, uint32_t& r2,
                                       uint32_t& r3, uint32_t saddr) {
    asm volatile("ldmatrix.sync.aligned.m8n8.x4.shared.b16 {%0,%1,%2,%3}, [%4];"
                 : "=r"(r0), "=r"(r1), "=r"(r2), "=r"(r3) : "r"(saddr));
}

__device__ __forceinline__ void mma_tf32(float* c, const uint32_t* a,
                                         uint32_t b0, uint32_t b1) {
    asm volatile(
        "mma.sync.aligned.m16n8k8.row.col.f32.tf32.tf32.f32 "
        "{%0,%1,%2,%3}, {%4,%5,%6,%7}, {%8,%9}, {%0,%1,%2,%3};"
        : "+f"(c[0]), "+f"(c[1]), "+f"(c[2]), "+f"(c[3])
        : "r"(a[0]), "r"(a[1]), "r"(a[2]), "r"(a[3]), "r"(b0), "r"(b1));
}

__device__ __forceinline__ void mma_bf16(float* c, const uint32_t* a,
                                         uint32_t b0, uint32_t b1) {
    asm volatile(
        "mma.sync.aligned.m16n8k16.row.col.f32.bf16.bf16.f32 "
        "{%0,%1,%2,%3}, {%4,%5,%6,%7}, {%8,%9}, {%0,%1,%2,%3};"
        : "+f"(c[0]), "+f"(c[1]), "+f"(c[2]), "+f"(c[3])
        : "r"(a[0]), "r"(a[1]), "r"(a[2]), "r"(a[3]), "r"(b0), "r"(b1));
}

// ---------------------------------------------------------------------------
// Prep: round x; round + transpose the four weight matrices.
// ---------------------------------------------------------------------------
__global__ void prep_x(const float* __restrict__ x) {
    int i = blockIdx.x * blockDim.x + threadIdx.x;       // float4 index
    float4 v = ((const float4*)x)[i];
    ((float4*)g_xr)[i] =
        make_float4(f2tff(v.x), f2tff(v.y), f2tff(v.z), f2tff(v.w));
}

__global__ void prep_w(const float* __restrict__ Wq, const float* __restrict__ Wk,
                       const float* __restrict__ Wv, const float* __restrict__ Wo) {
    __shared__ float t[32][33];
    const int z = blockIdx.z;
    const float* W = (z == 0) ? Wq : (z == 1) ? Wk : (z == 2) ? Wv : Wo;
    float* Wt = g_wt + (size_t)z * WSZ;
    const int bx = blockIdx.x * 32, by = blockIdx.y * 32;
    const int tx = threadIdx.x, ty = threadIdx.y;
    #pragma unroll
    for (int j = 0; j < 32; j += 8)
        t[ty + j][tx] = f2tff(W[(size_t)(by + ty + j) * EMB + bx + tx]);
    __syncthreads();
    #pragma unroll
    for (int j = 0; j < 32; j += 8)
        Wt[(size_t)(bx + ty + j) * EMB + by + tx] = t[tx][ty + j];
}

// ---------------------------------------------------------------------------
// Kernel 1: QKV projections. cp.async double-buffered tiles of pre-rounded
// g_xr / g_wt (transposed); all fragments via ldmatrix.x4; tf32 mma.
// Tile 128x64, K-step 32, warp m32n64. Dynamic smem 55296 B.
// ---------------------------------------------------------------------------
__global__ __launch_bounds__(128) void proj_qkv(
    const float* __restrict__ bq, const float* __restrict__ bk,
    const float* __restrict__ bv)
{
    extern __shared__ float sm[];
    float* As = sm;                        // [2][128][36]
    float* Bs = sm + 2 * 128 * 36;         // [2][64][36]
    const uint32_t as_u = (uint32_t)__cvta_generic_to_shared(As);
    const uint32_t bs_u = (uint32_t)__cvta_generic_to_shared(Bs);

    const int which = blockIdx.z;
    const float* Wt   = g_wt + (size_t)which * WSZ;
    const float* bias = (which == 0) ? bq : (which == 1) ? bk : bv;
    const int head = blockIdx.x;
    const int n0 = head * 64;
    const int m0 = blockIdx.y * 128;
    const int tid = threadIdx.x;
    const int lane = tid & 31, w = tid >> 5;
    const int g = lane >> 2, tig = lane & 3;
    const int lg = lane >> 3, lr7 = lane & 7;
    // A-frag matrices: {a0,a1,a2,a3} = {(+0r,+0w),(+8r,+0w),(+0r,+4w),(+8r,+4w)}
    const uint32_t a_off = ((lr7 + ((lg & 1) << 3)) * 36 + ((lg >> 1) << 2)) * 4;
    // B-frag matrices: {b0(n),b1(n),b0(n+1),b1(n+1)} = {(+0r,+0w),(+0r,+4w),(+8r,+0w),(+8r,+4w)}
    const uint32_t b_off = ((lr7 + ((lg >> 1) << 3)) * 36 + ((lg & 1) << 2)) * 4;

    float acc[2][8][4] = {};

    auto issue = [&](int buf, int k0) {
        #pragma unroll
        for (int rep = 0; rep < 8; rep++) {                    // X: 128 x 32
            int f = rep * 128 + tid, r = f >> 3, c = (f & 7) * 4;
            cp16(As + buf * (128 * 36) + r * 36 + c,
                 g_xr + (size_t)(m0 + r) * EMB + k0 + c);
        }
        #pragma unroll
        for (int rep = 0; rep < 4; rep++) {                    // W^T: 64 x 32
            int f = rep * 128 + tid, r = f >> 3, c = (f & 7) * 4;
            cp16(Bs + buf * (64 * 36) + r * 36 + c,
                 Wt + (size_t)(n0 + r) * EMB + k0 + c);
        }
        CP_COMMIT();
    };

    issue(0, 0);
    const int NKS = EMB / 32;
    for (int ks = 0; ks < NKS; ks++) {
        const int cb = ks & 1, nb = cb ^ 1;
        if (ks + 1 < NKS) {
            issue(nb, (ks + 1) * 32);
            asm volatile("cp.async.wait_group 1;" ::: "memory");
        } else {
            asm volatile("cp.async.wait_group 0;" ::: "memory");
        }
        __syncthreads();
        const uint32_t abase = as_u + cb * (128 * 36 * 4);
        const uint32_t bbase = bs_u + cb * (64 * 36 * 4);
        #pragma unroll
        for (int kh = 0; kh < 4; kh++) {
            uint32_t a[2][4];
            #pragma unroll
            for (int mt = 0; mt < 2; mt++)
                ldm_x4(a[mt][0], a[mt][1], a[mt][2], a[mt][3],
                       abase + (((w * 32 + mt * 16) * 36 + kh * 8) << 2) + a_off);
            #pragma unroll
            for (int n2 = 0; n2 < 4; n2++) {
                uint32_t r0, r1, r2, r3;
                ldm_x4(r0, r1, r2, r3,
                       bbase + (((n2 * 16) * 36 + kh * 8) << 2) + b_off);
                mma_tf32(acc[0][2 * n2],     a[0], r0, r1);
                mma_tf32(acc[1][2 * n2],     a[1], r0, r1);
                mma_tf32(acc[0][2 * n2 + 1], a[0], r2, r3);
                mma_tf32(acc[1][2 * n2 + 1], a[1], r2, r3);
            }
        }
        __syncthreads();
    }

    if (which == 0) {               // Q: fp32, row-major
        float* outp = g_q + (size_t)head * (SEQ * HD);
        #pragma unroll
        for (int mt = 0; mt < 2; mt++) {
            const int r0 = m0 + w * 32 + mt * 16 + g, r1 = r0 + 8;
            #pragma unroll
            for (int n = 0; n < 8; n++) {
                int cc = n * 8 + 2 * tig;
                float b0 = bias[n0 + cc], b1 = bias[n0 + cc + 1];
                *(float2*)&outp[(size_t)r0 * HD + cc] =
                    make_float2(acc[mt][n][0] + b0, acc[mt][n][1] + b1);
                *(float2*)&outp[(size_t)r1 * HD + cc] =
                    make_float2(acc[mt][n][2] + b0, acc[mt][n][3] + b1);
            }
        }
    } else if (which == 1) {        // K: bf16x2, row-major (d pairs)
        uint32_t* outp = g_kb + (size_t)head * (SEQ * HD / 2);
        #pragma unroll
        for (int mt = 0; mt < 2; mt++) {
            const int r0 = m0 + w * 32 + mt * 16 + g, r1 = r0 + 8;
            #pragma unroll
            for (int n = 0; n < 8; n++) {
                int cc = n * 8 + 2 * tig;
                float b0 = bias[n0 + cc], b1 = bias[n0 + cc + 1];
                outp[(size_t)r0 * 32 + n * 4 + tig] =
                    bf16x2(acc[mt][n][1] + b1, acc[mt][n][0] + b0);
                outp[(size_t)r1 * 32 + n * 4 + tig] =
                    bf16x2(acc[mt][n][3] + b1, acc[mt][n][2] + b0);
            }
        }
    } else {                        // V: bf16x2, transposed [d][key/2]
        uint32_t* outp = g_vb + (size_t)head * (HD * SEQ / 2);
        const bool evn = (lane & 4) == 0;
        #pragma unroll
        for (int mt = 0; mt < 2; mt++) {
            const int r0 = m0 + w * 32 + mt * 16 + g, r1 = r0 + 8;
            const int kw0 = r0 >> 1, kw1 = r1 >> 1;
            #pragma unroll
            for (int n = 0; n < 8; n++) {
                int cc = n * 8 + 2 * tig;
                float b0 = bias[n0 + cc], b1 = bias[n0 + cc + 1];
                uint32_t p0 = bf16x2(acc[mt][n][1] + b1, acc[mt][n][0] + b0);
                uint32_t p1 = bf16x2(acc[mt][n][3] + b1, acc[mt][n][2] + b0);
                uint32_t q0 = __shfl_xor_sync(0xffffffffu, p0, 4);
                uint32_t q1 = __shfl_xor_sync(0xffffffffu, p1, 4);
                if (evn) {
                    outp[(size_t)cc * (SEQ / 2) + kw0] = __byte_perm(p0, q0, 0x5410);
                    outp[(size_t)cc * (SEQ / 2) + kw1] = __byte_perm(p1, q1, 0x5410);
                } else {
                    outp[(size_t)(cc + 1) * (SEQ / 2) + kw0] = __byte_perm(p0, q0, 0x3276);
                    outp[(size_t)(cc + 1) * (SEQ / 2) + kw1] = __byte_perm(p1, q1, 0x3276);
                }
            }
        }
    }
}

// ---------------------------------------------------------------------------
// Kernel 2: flash attention (R9 structure). R10: K/V B-fragments loaded via
// ldmatrix.x4 (32 instr/warp/tile instead of 128 scalar LDS).
// ---------------------------------------------------------------------------
__global__ __launch_bounds__(128, 2) void attn_mma()
{
    __shared__ __align__(16) uint32_t Kb[2][64][36];   // [key][d/2]
    __shared__ __align__(16) uint32_t Vt[2][64][36];   // [d][key/2]

    const int head = blockIdx.y;
    const int q0 = blockIdx.x * 128;
    const float*    Qg = g_q  + (size_t)head * (SEQ * HD);
    const uint32_t* Kg = g_kb + (size_t)head * (SEQ * HD / 2);
    const uint32_t* Vg = g_vb + (size_t)head * (HD * SEQ / 2);
    const int tid  = threadIdx.x;
    const int lane = tid & 31, w = tid >> 5;
    const int g = lane >> 2, tig = lane & 3;
    const int lr = tid >> 3, lc4 = (tid & 7) * 4;
    const int lg = lane >> 3, lr7 = lane & 7;
    const uint32_t lm_off = ((lr7 + ((lg >> 1) << 3)) * 36 + ((lg & 1) << 2)) * 4;
    const uint32_t kb_u = (uint32_t)__cvta_generic_to_shared(&Kb[0][0][0]);
    const uint32_t vt_u = (uint32_t)__cvta_generic_to_shared(&Vt[0][0][0]);
    const uint32_t BUF = 64 * 36 * 4;

    uint32_t qa[2][4][4];
    #pragma unroll
    for (int mt = 0; mt < 2; mt++) {
        const float* qr0 = Qg + (size_t)(q0 + w * 32 + mt * 16 + g) * HD;
        const float* qr1 = qr0 + 8 * HD;
        #pragma unroll
        for (int kc = 0; kc < 4; kc++) {
            int d = kc * 16 + 2 * tig;
            qa[mt][kc][0] = bf16x2(qr0[d + 1] * 0.125f, qr0[d] * 0.125f);
            qa[mt][kc][1] = bf16x2(qr1[d + 1] * 0.125f, qr1[d] * 0.125f);
            qa[mt][kc][2] = bf16x2(qr0[d + 9] * 0.125f, qr0[d + 8] * 0.125f);
            qa[mt][kc][3] = bf16x2(qr1[d + 9] * 0.125f, qr1[d + 8] * 0.125f);
        }
    }

    float o[2][8][4] = {};
    float mi[2][2], li[2][2];
    #pragma unroll
    for (int mt = 0; mt < 2; mt++) {
        mi[mt][0] = -INFINITY; mi[mt][1] = -INFINITY;
        li[mt][0] = 0.f;       li[mt][1] = 0.f;
    }

    #pragma unroll
    for (int rep = 0; rep < 4; rep++) {
        int r = rep * 16 + lr;
        cp16(&Kb[0][r][lc4], &Kg[(size_t)r * 32 + lc4]);
        cp16(&Vt[0][r][lc4], &Vg[(size_t)r * (SEQ / 2) + lc4]);
    }
    CP_COMMIT();

    const int NT = SEQ / 64;
    for (int t = 0; t < NT; ++t) {
        const int cb = t & 1, nb = cb ^ 1;
        __syncthreads();

        if (t + 1 < NT) {
            const int kbase = (t + 1) * 64, wbase = (t + 1) * 32;
            #pragma unroll
            for (int rep = 0; rep < 4; rep++) {
                int r = rep * 16 + lr;
                cp16(&Kb[nb][r][lc4], &Kg[(size_t)(kbase + r) * 32 + lc4]);
                cp16(&Vt[nb][r][lc4], &Vg[(size_t)r * (SEQ / 2) + wbase + lc4]);
            }
            CP_COMMIT();
            asm volatile("cp.async.wait_group 1;" ::: "memory");
        } else {
            asm volatile("cp.async.wait_group 0;" ::: "memory");
        }
        __syncthreads();

        #pragma unroll
        for (int h = 0; h < 2; h++) {
            // S = Q K^T (B-frags via ldmatrix)
            float s[2][4][4] = {};
            #pragma unroll
            for (int kc = 0; kc < 4; kc++) {
                #pragma unroll
                for (int n2 = 0; n2 < 2; n2++) {
                    uint32_t r0, r1, r2, r3;
                    ldm_x4(r0, r1, r2, r3,
                           kb_u + cb * BUF +
                           (((h * 32 + n2 * 16) * 36 + kc * 8) << 2) + lm_off);
                    mma_bf16(s[0][2 * n2],     qa[0][kc], r0, r1);
                    mma_bf16(s[1][2 * n2],     qa[1][kc], r0, r1);
                    mma_bf16(s[0][2 * n2 + 1], qa[0][kc], r2, r3);
                    mma_bf16(s[1][2 * n2 + 1], qa[1][kc], r2, r3);
                }
            }

            // online softmax
            #pragma unroll
            for (int mt = 0; mt < 2; mt++) {
                float mx0 = -INFINITY, mx1 = -INFINITY;
                #pragma unroll
                for (int n = 0; n < 4; n++) {
                    mx0 = fmaxf(mx0, fmaxf(s[mt][n][0], s[mt][n][1]));
                    mx1 = fmaxf(mx1, fmaxf(s[mt][n][2], s[mt][n][3]));
                }
                mx0 = fmaxf(mx0, __shfl_xor_sync(0xffffffffu, mx0, 1));
                mx0 = fmaxf(mx0, __shfl_xor_sync(0xffffffffu, mx0, 2));
                mx1 = fmaxf(mx1, __shfl_xor_sync(0xffffffffu, mx1, 1));
                mx1 = fmaxf(mx1, __shfl_xor_sync(0xffffffffu, mx1, 2));
                float nm0 = fmaxf(mi[mt][0], mx0), nm1 = fmaxf(mi[mt][1], mx1);
                float sc0 = __expf(mi[mt][0] - nm0), sc1 = __expf(mi[mt][1] - nm1);
                mi[mt][0] = nm0; mi[mt][1] = nm1;
                float sum0 = 0.f, sum1 = 0.f;
                #pragma unroll
                for (int n = 0; n < 4; n++) {
                    s[mt][n][0] = __expf(s[mt][n][0] - nm0); sum0 += s[mt][n][0];
                    s[mt][n][1] = __expf(s[mt][n][1] - nm0); sum0 += s[mt][n][1];
                    s[mt][n][2] = __expf(s[mt][n][2] - nm1); sum1 += s[mt][n][2];
                    s[mt][n][3] = __expf(s[mt][n][3] - nm1); sum1 += s[mt][n][3];
                }
                sum0 += __shfl_xor_sync(0xffffffffu, sum0, 1);
                sum0 += __shfl_xor_sync(0xffffffffu, sum0, 2);
                sum1 += __shfl_xor_sync(0xffffffffu, sum1, 1);
                sum1 += __shfl_xor_sync(0xffffffffu, sum1, 2);
                li[mt][0] = li[mt][0] * sc0 + sum0;
                li[mt][1] = li[mt][1] * sc1 + sum1;
                #pragma unroll
                for (int n = 0; n < 8; n++) {
                    o[mt][n][0] *= sc0; o[mt][n][1] *= sc0;
                    o[mt][n][2] *= sc1; o[mt][n][3] *= sc1;
                }
            }

            // P: C-frags -> bf16 A-frags
            uint32_t pk[2][2][4];
            #pragma unroll
            for (int mt = 0; mt < 2; mt++)
                #pragma unroll
                for (int kc2 = 0; kc2 < 2; kc2++) {
                    pk[mt][kc2][0] = bf16x2(s[mt][2*kc2  ][1], s[mt][2*kc2  ][0]);
                    pk[mt][kc2][1] = bf16x2(s[mt][2*kc2  ][3], s[mt][2*kc2  ][2]);
                    pk[mt][kc2][2] = bf16x2(s[mt][2*kc2+1][1], s[mt][2*kc2+1][0]);
                    pk[mt][kc2][3] = bf16x2(s[mt][2*kc2+1][3], s[mt][2*kc2+1][2]);
                }

            // O += P V (B-frags via ldmatrix)
            #pragma unroll
            for (int kc2 = 0; kc2 < 2; kc2++) {
                #pragma unroll
                for (int n2 = 0; n2 < 4; n2++) {
                    uint32_t r0, r1, r2, r3;
                    ldm_x4(r0, r1, r2, r3,
                           vt_u + cb * BUF +
                           (((n2 * 16) * 36 + h * 16 + kc2 * 8) << 2) + lm_off);
                    mma_bf16(o[0][2 * n2],     pk[0][kc2], r0, r1);
                    mma_bf16(o[1][2 * n2],     pk[1][kc2], r0, r1);
                    mma_bf16(o[0][2 * n2 + 1], pk[0][kc2], r2, r3);
                    mma_bf16(o[1][2 * n2 + 1], pk[1][kc2], r2, r3);
                }
            }
        }
    }

    float* Og = g_attn + (size_t)head * (SEQ * HD);
    #pragma unroll
    for (int mt = 0; mt < 2; mt++) {
        float inv0 = 1.0f / li[mt][0], inv1 = 1.0f / li[mt][1];
        const int r0 = q0 + w * 32 + mt * 16 + g, r1 = r0 + 8;
        #pragma unroll
        for (int n = 0; n < 8; n++) {
            int cc = n * 8 + 2 * tig;
            *(float2*)&Og[(size_t)r0 * HD + cc] = make_float2(
                f2tff(o[mt][n][0] * inv0), f2tff(o[mt][n][1] * inv0));
            *(float2*)&Og[(size_t)r1 * HD + cc] = make_float2(
                f2tff(o[mt][n][2] * inv1), f2tff(o[mt][n][3] * inv1));
        }
    }
}

// ---------------------------------------------------------------------------
// Kernel 3: output projection — same machinery as proj_qkv; A tiles gathered
// from g_attn (pre-rounded by attn epilogue), B from transposed rounded Wo.
// ---------------------------------------------------------------------------
__global__ __launch_bounds__(128) void proj_out(
    const float* __restrict__ bo, float* __restrict__ out)
{
    extern __shared__ float sm[];
    float* As = sm;                        // [2][128][36]
    float* Bs = sm + 2 * 128 * 36;         // [2][64][36]
    const uint32_t as_u = (uint32_t)__cvta_generic_to_shared(As);
    const uint32_t bs_u = (uint32_t)__cvta_generic_to_shared(Bs);
    const float* Wt = g_wt + (size_t)3 * WSZ;

    const int n0 = blockIdx.x * 64;
    const int m0 = blockIdx.y * 128;
    const int tid = threadIdx.x;
    const int lane = tid & 31, w = tid >> 5;
    const int g = lane >> 2, tig = lane & 3;
    const int lg = lane >> 3, lr7 = lane & 7;
    const uint32_t a_off = ((lr7 + ((lg & 1) << 3)) * 36 + ((lg >> 1) << 2)) * 4;
    const uint32_t b_off = ((lr7 + ((lg >> 1) << 3)) * 36 + ((lg & 1) << 2)) * 4;

    float acc[2][8][4] = {};

    auto issue = [&](int buf, int k0) {
        const int h = k0 >> 6, d0 = k0 & 63;
        #pragma unroll
        for (int rep = 0; rep < 8; rep++) {
            int f = rep * 128 + tid, r = f >> 3, c = (f & 7) * 4;
            cp16(As + buf * (128 * 36) + r * 36 + c,
                 g_attn + ((size_t)h * SEQ + m0 + r) * HD + d0 + c);
        }
        #pragma unroll
        for (int rep = 0; rep < 4; rep++) {
            int f = rep * 128 + tid, r = f >> 3, c = (f & 7) * 4;
            cp16(Bs + buf * (64 * 36) + r * 36 + c,
                 Wt + (size_t)(n0 + r) * EMB + k0 + c);
        }
        CP_COMMIT();
    };

    issue(0, 0);
    const int NKS = EMB / 32;
    for (int ks = 0; ks < NKS; ks++) {
        const int cb = ks & 1, nb = cb ^ 1;
        if (ks + 1 < NKS) {
            issue(nb, (ks + 1) * 32);
            asm volatile("cp.async.wait_group 1;" ::: "memory");
        } else {
            asm volatile("cp.async.wait_group 0;" ::: "memory");
        }
        __syncthreads();
        const uint32_t abase = as_u + cb * (128 * 36 * 4);
        const uint32_t bbase = bs_u + cb * (64 * 36 * 4);
        #pragma unroll
        for (int kh = 0; kh < 4; kh++) {
            uint32_t a[2][4];
            #pragma unroll
            for (int mt = 0; mt < 2; mt++)
                ldm_x4(a[mt][0], a[mt][1], a[mt][2], a[mt][3],
                       abase + (((w * 32 + mt * 16) * 36 + kh * 8) << 2) + a_off);
            #pragma unroll
            for (int n2 = 0; n2 < 4; n2++) {
                uint32_t r0, r1, r2, r3;
                ldm_x4(r0, r1, r2, r3,
                       bbase + (((n2 * 16) * 36 + kh * 8) << 2) + b_off);
                mma_tf32(acc[0][2 * n2],     a[0], r0, r1);
                mma_tf32(acc[1][2 * n2],     a[1], r0, r1);
                mma_tf32(acc[0][2 * n2 + 1], a[0], r2, r3);
                mma_tf32(acc[1][2 * n2 + 1], a[1], r2, r3);
            }
        }
        __syncthreads();
    }

    #pragma unroll
    for (int mt = 0; mt < 2; mt++) {
        const int r0 = m0 + w * 32 + mt * 16 + g, r1 = r0 + 8;
        #pragma unroll
        for (int n = 0; n < 8; n++) {
            int cc = n0 + n * 8 + 2 * tig;
            float b0 = bo[cc], b1 = bo[cc + 1];
            *(float2*)&out[(size_t)r0 * EMB + cc] =
                make_float2(acc[mt][n][0] + b0, acc[mt][n][1] + b1);
            *(float2*)&out[(size_t)r1 * EMB + cc] =
                make_float2(acc[mt][n][2] + b0, acc[mt][n][3] + b1);
        }
    }
}

// ---------------------------------------------------------------------------
// Launch. Input order (metadata): x, Wk, bk, Wq, bq, Wv, bv, Wo, bo.
// ---------------------------------------------------------------------------
extern "C" void kernel_launch(void* const* d_in, const int* in_sizes, int n_in,
                              void* d_out, int out_size)
{
    const float* x  = (const float*)d_in[0];
    const float* Wk = (const float*)d_in[1];
    const float* bk = (const float*)d_in[2];
    const float* Wq = (const float*)d_in[3];
    const float* bq = (const float*)d_in[4];
    const float* Wv = (const float*)d_in[5];
    const float* bv = (const float*)d_in[6];
    const float* Wo = (const float*)d_in[7];
    const float* bo = (const float*)d_in[8];
    float* out = (float*)d_out;

    const int smemP = (2 * 128 * 36 + 2 * 64 * 36) * (int)sizeof(float);  // 55296
    cudaFuncSetAttribute(proj_qkv, cudaFuncAttributeMaxDynamicSharedMemorySize, smemP);
    cudaFuncSetAttribute(proj_out, cudaFuncAttributeMaxDynamicSharedMemorySize, smemP);

    prep_x<<<SEQ * EMB / 4 / 256, 256>>>(x);
    prep_w<<<dim3(EMB / 32, EMB / 32, 4), dim3(32, 8)>>>(Wq, Wk, Wv, Wo);
    proj_qkv<<<dim3(NH, SEQ / 128, 3), 128, smemP>>>(bq, bk, bv);
    attn_mma<<<dim3(SEQ / 128, NH), 128>>>();
    proj_out<<<dim3(EMB / 64, SEQ / 128), 128, smemP>>>(bo, out);
}